// round 2
// baseline (speedup 1.0000x reference)
#include <cuda_runtime.h>
#include <math.h>

// ---------------- problem constants ----------------
#define NT   16384          // tokens (B*S)
#define NK   32768          // tokens * TOP_K
#define D_   768
#define H_   2048
#define E_   8
#define CAP  5120           // ceil(1.25 * 2 * 16384 / 8)
#define EPSF 1e-6f

// ---------------- device scratch (allowed: __device__ globals) ----------------
__device__ float g_xn  [(size_t)NT * D_];            // rmsnorm(2x) per token
__device__ float g_zbuf[(size_t)E_ * CAP * D_];      // dispatched z rows (slot-major)
__device__ float g_gu  [(size_t)E_ * CAP * 2 * H_];  // GEMM1 out
__device__ float g_act [(size_t)E_ * CAP * H_];      // silu(g)*u
__device__ float g_ffn [(size_t)E_ * CAP * D_];      // GEMM2 out
__device__ int   g_rowlist[E_ * CAP];                // slot -> flat index
__device__ int   g_cnt[E_];
__device__ int   g_slot[NK];                         // flat -> slot (or -1 dropped)
__device__ int   g_expert[NK];
__device__ float g_weight[NK];

// ---------------- 1) per-token RMS of 2x ----------------
__global__ void rms_kernel(const float* __restrict__ x) {
    int t = blockIdx.x;
    const float* xp = x + (size_t)t * D_;
    float ss = 0.f;
    for (int i = threadIdx.x; i < D_; i += 256) { float v = xp[i]; ss += v * v; }
    for (int o = 16; o; o >>= 1) ss += __shfl_xor_sync(0xffffffffu, ss, o);
    __shared__ float red[8];
    __shared__ float s_scale;
    if ((threadIdx.x & 31) == 0) red[threadIdx.x >> 5] = ss;
    __syncthreads();
    if (threadIdx.x == 0) {
        float tot = 0.f;
        #pragma unroll
        for (int j = 0; j < 8; j++) tot += red[j];
        // z = 2x * rsqrt(mean((2x)^2) + eps) = 2x * rsqrt(4*sum(x^2)/D + eps)
        s_scale = 2.f * rsqrtf(4.f * tot / (float)D_ + EPSF);
    }
    __syncthreads();
    float sc = s_scale;
    for (int i = threadIdx.x; i < D_; i += 256)
        g_xn[(size_t)t * D_ + i] = xp[i] * sc;
}

// ---------------- 2) router: logits, top-2, renormalized weights ----------------
__global__ void router_kernel(const float* __restrict__ x, const float* __restrict__ gw) {
    __shared__ float sgw[E_ * D_];
    for (int i = threadIdx.x; i < E_ * D_; i += 256) sgw[i] = gw[i];
    __syncthreads();
    int lane = threadIdx.x & 31, warp = threadIdx.x >> 5;
    int t = blockIdx.x * 8 + warp;
    const float* xp = x + (size_t)t * D_;
    float xr[24];
    #pragma unroll
    for (int j = 0; j < 24; j++) xr[j] = xp[lane + 32 * j];
    float logit[E_];
    #pragma unroll
    for (int e = 0; e < E_; e++) {
        float acc = 0.f;
        #pragma unroll
        for (int j = 0; j < 24; j++) acc += xr[j] * sgw[e * D_ + lane + 32 * j];
        for (int o = 16; o; o >>= 1) acc += __shfl_xor_sync(0xffffffffu, acc, o);
        logit[e] = acc;
    }
    if (lane == 0) {
        int i0 = 0; float l0 = logit[0];
        #pragma unroll
        for (int e = 1; e < E_; e++) if (logit[e] > l0) { l0 = logit[e]; i0 = e; }
        int i1 = -1; float l1 = -3.0e38f;
        #pragma unroll
        for (int e = 0; e < E_; e++) if (e != i0 && logit[e] > l1) { l1 = logit[e]; i1 = e; }
        // p0/(p0+p1) with p = softmax(logits): = 1/(1+e^{l1-l0})
        float w0 = 1.f / (1.f + expf(l1 - l0));
        g_expert[2 * t]     = i0;
        g_expert[2 * t + 1] = i1;
        g_weight[2 * t]     = w0;
        g_weight[2 * t + 1] = 1.f - w0;
    }
}

// ---------------- 3) exact flat-order capacity scan (one block per expert) ----------------
__global__ void scan_kernel() {
    int e = blockIdx.x;
    int tid = threadIdx.x;
    __shared__ int warpsum[8];
    __shared__ int sbase;
    if (tid == 0) sbase = 0;
    __syncthreads();
    for (int i0 = 0; i0 < NK; i0 += 256) {
        int i = i0 + tid;
        int mine = (g_expert[i] == e) ? 1 : 0;
        unsigned m = __ballot_sync(0xffffffffu, mine);
        int lane = tid & 31, w = tid >> 5;
        if (lane == 0) warpsum[w] = __popc(m);
        __syncthreads();
        int off = 0, tot = 0;
        #pragma unroll
        for (int j = 0; j < 8; j++) { int c = warpsum[j]; tot += c; if (j < w) off += c; }
        int rank = sbase + off + __popc(m & ((1u << lane) - 1u));
        if (mine) {
            if (rank < CAP) { g_rowlist[e * CAP + rank] = i; g_slot[i] = e * CAP + rank; }
            else            { g_slot[i] = -1; }
        }
        __syncthreads();
        if (tid == 0) sbase += tot;
    }
    __syncthreads();
    if (tid == 0) g_cnt[e] = (sbase < CAP) ? sbase : CAP;
}

// ---------------- 4) dispatch: zbuf[slot] = xn[token] * norm_w[e] ----------------
__global__ void dispatch_kernel(const float* __restrict__ norm_w) {
    int slot = blockIdx.x;
    int e = slot / CAP, r = slot % CAP;
    if (r >= g_cnt[e]) return;
    int flat = g_rowlist[slot];
    int t = flat >> 1;
    const float4* src = (const float4*)(g_xn + (size_t)t * D_);
    const float4* nw  = (const float4*)(norm_w + (size_t)e * D_);
    float4* dst = (float4*)(g_zbuf + (size_t)slot * D_);
    int i = threadIdx.x;  // 192 threads, 192*4 = 768
    float4 a = src[i], b = nw[i];
    dst[i] = make_float4(a.x * b.x, a.y * b.y, a.z * b.z, a.w * b.w);
}

// ---------------- 5/7) grouped SGEMM  C[m,n] = sum_k A[m,k]*B[n,k] ----------------
#define BM 128
#define BN 128
#define BK 16

__global__ __launch_bounds__(256, 2) void gemm_tn(
    const float* __restrict__ Ball, int K, int N, int which)
{
    int e  = blockIdx.z;
    int m0 = blockIdx.y * BM;
    if (m0 >= g_cnt[e]) return;   // cnt-bounded tile early exit
    int n0 = blockIdx.x * BN;

    const float* Aall = which ? g_act : g_zbuf;
    float*       Call = which ? g_ffn : g_gu;

    const float* A = Aall + (size_t)e * CAP * K + (size_t)m0 * K;
    const float* B = Ball + (size_t)e * N   * K + (size_t)n0 * K;
    float*       C = Call + (size_t)e * CAP * N + (size_t)m0 * N + n0;

    __shared__ float As[BK][BM + 4];
    __shared__ float Bs[BK][BN + 4];

    int tid = threadIdx.x;
    int tx = tid & 15, ty = tid >> 4;

    float acc[8][8];
    #pragma unroll
    for (int i = 0; i < 8; i++)
        #pragma unroll
        for (int j = 0; j < 8; j++) acc[i][j] = 0.f;

    for (int k0 = 0; k0 < K; k0 += BK) {
        #pragma unroll
        for (int l = 0; l < 2; l++) {
            int li = tid + l * 256;           // 512 float4 per tile
            int row = li >> 2, kc = (li & 3) << 2;
            float4 va = *(const float4*)(A + (size_t)row * K + k0 + kc);
            As[kc + 0][row] = va.x; As[kc + 1][row] = va.y;
            As[kc + 2][row] = va.z; As[kc + 3][row] = va.w;
            float4 vb = *(const float4*)(B + (size_t)row * K + k0 + kc);
            Bs[kc + 0][row] = vb.x; Bs[kc + 1][row] = vb.y;
            Bs[kc + 2][row] = vb.z; Bs[kc + 3][row] = vb.w;
        }
        __syncthreads();
        #pragma unroll
        for (int kk = 0; kk < BK; kk++) {
            float a[8], b[8];
            *(float4*)(a)     = *(const float4*)(&As[kk][ty * 8]);
            *(float4*)(a + 4) = *(const float4*)(&As[kk][ty * 8 + 4]);
            *(float4*)(b)     = *(const float4*)(&Bs[kk][tx * 8]);
            *(float4*)(b + 4) = *(const float4*)(&Bs[kk][tx * 8 + 4]);
            #pragma unroll
            for (int i = 0; i < 8; i++)
                #pragma unroll
                for (int j = 0; j < 8; j++)
                    acc[i][j] += a[i] * b[j];
        }
        __syncthreads();
    }
    #pragma unroll
    for (int i = 0; i < 8; i++) {
        float* cp = C + (size_t)(ty * 8 + i) * N + tx * 8;
        #pragma unroll
        for (int j = 0; j < 8; j += 4)
            *(float4*)(cp + j) = make_float4(acc[i][j], acc[i][j + 1],
                                             acc[i][j + 2], acc[i][j + 3]);
    }
}

// ---------------- 6) act = silu(g) * u ----------------
__global__ void silu_kernel() {
    int row = blockIdx.x;
    int e = row / CAP;
    if (row % CAP >= g_cnt[e]) return;
    const float* gu = g_gu + (size_t)row * 2 * H_;
    float* act = g_act + (size_t)row * H_;
    for (int i = threadIdx.x; i < H_; i += 256) {
        float g = gu[i], u = gu[i + H_];
        act[i] = u * (g / (1.f + expf(-g)));
    }
}

// ---------------- 8) combine: out[t] = sum_k kept_k * w_k * (x[t] + ffn_k) ----------------
__global__ void combine_kernel(const float* __restrict__ x, float* __restrict__ out) {
    int t = blockIdx.x;
    int s0 = g_slot[2 * t], s1 = g_slot[2 * t + 1];
    float w0 = g_weight[2 * t], w1 = g_weight[2 * t + 1];
    int i = threadIdx.x;  // 192 threads
    float4 xv = ((const float4*)(x + (size_t)t * D_))[i];
    float rx = 0.f, ry = 0.f, rz = 0.f, rw = 0.f;
    if (s0 >= 0) {
        float4 f = ((const float4*)(g_ffn + (size_t)s0 * D_))[i];
        rx += w0 * (xv.x + f.x); ry += w0 * (xv.y + f.y);
        rz += w0 * (xv.z + f.z); rw += w0 * (xv.w + f.w);
    }
    if (s1 >= 0) {
        float4 f = ((const float4*)(g_ffn + (size_t)s1 * D_))[i];
        rx += w1 * (xv.x + f.x); ry += w1 * (xv.y + f.y);
        rz += w1 * (xv.z + f.z); rw += w1 * (xv.w + f.w);
    }
    ((float4*)(out + (size_t)t * D_))[i] = make_float4(rx, ry, rz, rw);
}

// ---------------- launch ----------------
extern "C" void kernel_launch(void* const* d_in, const int* in_sizes, int n_in,
                              void* d_out, int out_size) {
    const float* x      = (const float*)d_in[0];  // [4,4096,768]
    const float* gate_w = (const float*)d_in[1];  // [8,768]
    const float* w13    = (const float*)d_in[2];  // [8,4096,768]
    const float* w2     = (const float*)d_in[3];  // [8,768,2048]
    const float* norm_w = (const float*)d_in[4];  // [8,768]
    float* out = (float*)d_out;

    rms_kernel<<<NT, 256>>>(x);
    router_kernel<<<NT / 8, 256>>>(x, gate_w);
    scan_kernel<<<E_, 256>>>();
    dispatch_kernel<<<E_ * CAP, 192>>>(norm_w);

    dim3 g1(2 * H_ / BN, (CAP + BM - 1) / BM, E_);   // (32, 40, 8)
    gemm_tn<<<g1, 256>>>(w13, D_, 2 * H_, 0);

    silu_kernel<<<E_ * CAP, 256>>>();

    dim3 g2(D_ / BN, (CAP + BM - 1) / BM, E_);       // (6, 40, 8)
    gemm_tn<<<g2, 256>>>(w2, H_, D_, 1);

    combine_kernel<<<NT, 192>>>(x, out);
}

// round 7
// speedup vs baseline: 2.5503x; 2.5503x over previous
#include <cuda_runtime.h>
#include <cuda_fp16.h>
#include <math.h>
#include <stdint.h>

// ---------------- problem constants ----------------
#define NT   16384
#define NK   32768
#define D_   768
#define H_   2048
#define E_   8
#define CAP  5120
#define EPSF 1e-6f
#define N13  4096

#define RS    48        // smem row stride bytes (16 halves = 32B data + 16B pad)
#define REG   6144      // 128 rows * 48B per operand region
#define STG   18432     // Ah + Al + B regions

// ---------------- device scratch (referenced ONLY in device code) ----------------
__device__ float  g_xn  [(size_t)NT * D_];
__device__ __half g_zh  [(size_t)E_ * CAP * D_];
__device__ __half g_zl  [(size_t)E_ * CAP * D_];
__device__ __half g_w13h[(size_t)E_ * N13 * D_];
__device__ __half g_w2h [(size_t)E_ * D_ * H_];
__device__ float  g_gu  [(size_t)E_ * CAP * 2 * H_];
__device__ __half g_acth[(size_t)E_ * CAP * H_];
__device__ __half g_actl[(size_t)E_ * CAP * H_];
__device__ float  g_ffn [(size_t)E_ * CAP * D_];
__device__ int    g_rowlist[E_ * CAP];
__device__ int    g_cnt[E_];
__device__ int    g_slot[NK];
__device__ int    g_expert[NK];
__device__ float  g_weight[NK];

// ---------------- helpers ----------------
__device__ __forceinline__ uint32_t smem_u32(const void* p) {
    uint32_t a;
    asm("{ .reg .u64 t; cvta.to.shared.u64 t, %1; cvt.u32.u64 %0, t; }" : "=r"(a) : "l"(p));
    return a;
}
__device__ __forceinline__ uint32_t lds32(uint32_t addr) {
    uint32_t v;
    asm volatile("ld.shared.b32 %0, [%1];" : "=r"(v) : "r"(addr));
    return v;
}
__device__ __forceinline__ void mma16816(float* d, const uint32_t* a, uint32_t b0, uint32_t b1) {
    asm volatile(
        "mma.sync.aligned.m16n8k16.row.col.f32.f16.f16.f32 "
        "{%0,%1,%2,%3},{%4,%5,%6,%7},{%8,%9},{%0,%1,%2,%3};"
        : "+f"(d[0]), "+f"(d[1]), "+f"(d[2]), "+f"(d[3])
        : "r"(a[0]), "r"(a[1]), "r"(a[2]), "r"(a[3]), "r"(b0), "r"(b1));
}
__device__ __forceinline__ void cp16(uint32_t saddr, const void* g) {
    asm volatile("cp.async.cg.shared.global [%0], [%1], 16;" :: "r"(saddr), "l"(g) : "memory");
}
__device__ __forceinline__ void splith(float x, __half& h, __half& l) {
    h = __float2half_rn(x);
    l = __float2half_rn(x - __half2float(h));
}

// ---------------- 1) rmsnorm(2x) ----------------
__global__ void rms_kernel(const float* __restrict__ x) {
    int t = blockIdx.x;
    const float* xp = x + (size_t)t * D_;
    float ss = 0.f;
    for (int i = threadIdx.x; i < D_; i += 256) { float v = xp[i]; ss += v * v; }
    for (int o = 16; o; o >>= 1) ss += __shfl_xor_sync(0xffffffffu, ss, o);
    __shared__ float red[8];
    __shared__ float s_scale;
    if ((threadIdx.x & 31) == 0) red[threadIdx.x >> 5] = ss;
    __syncthreads();
    if (threadIdx.x == 0) {
        float tot = 0.f;
        #pragma unroll
        for (int j = 0; j < 8; j++) tot += red[j];
        s_scale = 2.f * rsqrtf(4.f * tot / (float)D_ + EPSF);
    }
    __syncthreads();
    float sc = s_scale;
    for (int i = threadIdx.x; i < D_; i += 256)
        g_xn[(size_t)t * D_ + i] = xp[i] * sc;
}

// ---------------- 2) router ----------------
__global__ void router_kernel(const float* __restrict__ x, const float* __restrict__ gw) {
    __shared__ float sgw[E_ * D_];
    for (int i = threadIdx.x; i < E_ * D_; i += 256) sgw[i] = gw[i];
    __syncthreads();
    int lane = threadIdx.x & 31, warp = threadIdx.x >> 5;
    int t = blockIdx.x * 8 + warp;
    const float* xp = x + (size_t)t * D_;
    float xr[24];
    #pragma unroll
    for (int j = 0; j < 24; j++) xr[j] = xp[lane + 32 * j];
    float logit[E_];
    #pragma unroll
    for (int e = 0; e < E_; e++) {
        float acc = 0.f;
        #pragma unroll
        for (int j = 0; j < 24; j++) acc += xr[j] * sgw[e * D_ + lane + 32 * j];
        for (int o = 16; o; o >>= 1) acc += __shfl_xor_sync(0xffffffffu, acc, o);
        logit[e] = acc;
    }
    if (lane == 0) {
        int i0 = 0; float l0 = logit[0];
        #pragma unroll
        for (int e = 1; e < E_; e++) if (logit[e] > l0) { l0 = logit[e]; i0 = e; }
        int i1 = -1; float l1 = -3.0e38f;
        #pragma unroll
        for (int e = 0; e < E_; e++) if (e != i0 && logit[e] > l1) { l1 = logit[e]; i1 = e; }
        float w0 = 1.f / (1.f + expf(l1 - l0));
        g_expert[2 * t]     = i0;
        g_expert[2 * t + 1] = i1;
        g_weight[2 * t]     = w0;
        g_weight[2 * t + 1] = 1.f - w0;
    }
}

// ---------------- 3) capacity scan ----------------
__global__ void scan_kernel() {
    int e = blockIdx.x;
    int tid = threadIdx.x;
    __shared__ int warpsum[8];
    __shared__ int sbase;
    if (tid == 0) sbase = 0;
    __syncthreads();
    for (int i0 = 0; i0 < NK; i0 += 256) {
        int i = i0 + tid;
        int mine = (g_expert[i] == e) ? 1 : 0;
        unsigned m = __ballot_sync(0xffffffffu, mine);
        int lane = tid & 31, w = tid >> 5;
        if (lane == 0) warpsum[w] = __popc(m);
        __syncthreads();
        int off = 0, tot = 0;
        #pragma unroll
        for (int j = 0; j < 8; j++) { int c = warpsum[j]; tot += c; if (j < w) off += c; }
        int rank = sbase + off + __popc(m & ((1u << lane) - 1u));
        if (mine) {
            if (rank < CAP) { g_rowlist[e * CAP + rank] = i; g_slot[i] = e * CAP + rank; }
            else            { g_slot[i] = -1; }
        }
        __syncthreads();
        if (tid == 0) sbase += tot;
    }
    __syncthreads();
    if (tid == 0) g_cnt[e] = (sbase < CAP) ? sbase : CAP;
}

// ---------------- 4) dispatch -> fp16 hi/lo ----------------
__global__ void dispatch_kernel(const float* __restrict__ norm_w) {
    int slot = blockIdx.x;
    int e = slot / CAP, r = slot % CAP;
    if (r >= g_cnt[e]) return;
    int t = g_rowlist[slot] >> 1;
    int i = threadIdx.x;  // 192 threads * 4 = 768
    float4 a = ((const float4*)(g_xn + (size_t)t * D_))[i];
    float4 b = ((const float4*)(norm_w + (size_t)e * D_))[i];
    float z[4] = { a.x * b.x, a.y * b.y, a.z * b.z, a.w * b.w };
    union { __half h[4]; uint2 u; } Hh, Ll;
    #pragma unroll
    for (int j = 0; j < 4; j++) splith(z[j], Hh.h[j], Ll.h[j]);
    ((uint2*)(g_zh + (size_t)slot * D_))[i] = Hh.u;
    ((uint2*)(g_zl + (size_t)slot * D_))[i] = Ll.u;
}

// ---------------- weights fp32 -> fp16 (dst selected in DEVICE code) -------
__global__ void cvt_kernel(const float* __restrict__ src, int which) {
    __half* dst = which ? g_w2h : g_w13h;
    int i = blockIdx.x * 256 + threadIdx.x;
    float4 v = ((const float4*)src)[i];
    union { __half h[4]; uint2 u; } H;
    H.h[0] = __float2half_rn(v.x); H.h[1] = __float2half_rn(v.y);
    H.h[2] = __float2half_rn(v.z); H.h[3] = __float2half_rn(v.w);
    ((uint2*)dst)[i] = H.u;
}

// ---------------- grouped GEMM via mma.sync (buffers selected in DEVICE code)
// C[m,n] = sum_k A[m,k]*B[n,k], A = Ah + Al (fp16 split), B fp16.
// Tile 128x128, KCH=16, double-buffered cp.async, 48B padded rows.
__global__ __launch_bounds__(256) void gemm_mma(int which, int K, int Ntot)
{
    __shared__ __align__(16) char sm[2][STG];

    const __half* Ahg = which ? g_acth : g_zh;
    const __half* Alg = which ? g_actl : g_zl;
    const __half* Bg  = which ? g_w2h  : g_w13h;
    float*        Cg  = which ? g_ffn  : g_gu;

    int e = blockIdx.z;
    int m0 = blockIdx.y * 128;
    if (m0 >= g_cnt[e]) return;
    int n0 = blockIdx.x * 128;

    int tid = threadIdx.x, lane = tid & 31, wid = tid >> 5;
    int wm = wid & 1, wn = wid >> 1;           // 2x4 warp grid, warp tile 64x32
    int g = lane >> 2, q = lane & 3;

    const __half* pAh = Ahg + ((size_t)e * CAP + m0) * K;
    const __half* pAl = Alg + ((size_t)e * CAP + m0) * K;
    const __half* pB  = Bg  + ((size_t)e * Ntot + n0) * K;

    float acc[4][4][4];
    #pragma unroll
    for (int i = 0; i < 4; i++)
        #pragma unroll
        for (int j = 0; j < 4; j++)
            #pragma unroll
            for (int p = 0; p < 4; p++) acc[i][j][p] = 0.f;

    int row_ld = tid >> 1, half_ld = tid & 1;            // 256 threads: 128 rows x 2 chunks
    uint32_t soff_ld = (uint32_t)row_ld * RS + (uint32_t)half_ld * 16;
    size_t goff_base = (size_t)row_ld * K + half_ld * 8;

    int NCH = K >> 4;

    // prologue: stages 0,1
    #pragma unroll
    for (int c = 0; c < 2; c++) {
        uint32_t sb = smem_u32(sm[c]);
        size_t go = goff_base + c * 16;
        cp16(sb + soff_ld,           pAh + go);
        cp16(sb + REG + soff_ld,     pAl + go);
        cp16(sb + 2 * REG + soff_ld, pB  + go);
        asm volatile("cp.async.commit_group;" ::: "memory");
    }

    for (int c = 0; c < NCH; c++) {
        asm volatile("cp.async.wait_group %0;" :: "n"(1) : "memory");
        __syncthreads();

        uint32_t sb = smem_u32(sm[c & 1]);
        uint32_t kb = (uint32_t)q * 4;       // byte offset of the thread's k-pair

        // B fragments: n = wn*32 + nf*8 + g ; b0 = k[2q..2q+1], b1 = k[2q+8..]
        uint32_t bfr[4][2];
        #pragma unroll
        for (int nf = 0; nf < 4; nf++) {
            uint32_t bo = sb + 2 * REG + (uint32_t)(wn * 32 + nf * 8 + g) * RS + kb;
            bfr[nf][0] = lds32(bo);
            bfr[nf][1] = lds32(bo + 16);
        }
        #pragma unroll
        for (int mf = 0; mf < 4; mf++) {
            uint32_t ao = sb + (uint32_t)(wm * 64 + mf * 16 + g) * RS + kb;
            uint32_t ah[4], al[4];
            ah[0] = lds32(ao);
            ah[1] = lds32(ao + 8 * RS);
            ah[2] = lds32(ao + 16);
            ah[3] = lds32(ao + 8 * RS + 16);
            al[0] = lds32(ao + REG);
            al[1] = lds32(ao + REG + 8 * RS);
            al[2] = lds32(ao + REG + 16);
            al[3] = lds32(ao + REG + 8 * RS + 16);
            #pragma unroll
            for (int nf = 0; nf < 4; nf++) {
                mma16816(acc[mf][nf], ah, bfr[nf][0], bfr[nf][1]);
                mma16816(acc[mf][nf], al, bfr[nf][0], bfr[nf][1]);
            }
        }
        __syncthreads();   // all reads of buffer (c&1) done before refill
        if (c + 2 < NCH) {
            uint32_t sb2 = smem_u32(sm[c & 1]);
            size_t go = goff_base + (size_t)(c + 2) * 16;
            cp16(sb2 + soff_ld,           pAh + go);
            cp16(sb2 + REG + soff_ld,     pAl + go);
            cp16(sb2 + 2 * REG + soff_ld, pB  + go);
        }
        asm volatile("cp.async.commit_group;" ::: "memory");
    }

    float* C = Cg + ((size_t)e * CAP + m0) * Ntot + n0;
    #pragma unroll
    for (int mf = 0; mf < 4; mf++)
        #pragma unroll
        for (int nf = 0; nf < 4; nf++) {
            int r0 = wm * 64 + mf * 16 + g;
            int col = wn * 32 + nf * 8 + q * 2;
            *(float2*)(C + (size_t)r0 * Ntot + col) =
                make_float2(acc[mf][nf][0], acc[mf][nf][1]);
            *(float2*)(C + (size_t)(r0 + 8) * Ntot + col) =
                make_float2(acc[mf][nf][2], acc[mf][nf][3]);
        }
}

// ---------------- 6) silu -> act fp16 hi/lo ----------------
__global__ void silu_kernel() {
    int row = blockIdx.x;
    int e = row / CAP;
    if (row % CAP >= g_cnt[e]) return;
    const float4* gp = (const float4*)(g_gu + (size_t)row * 2 * H_);
    uint2* ah = (uint2*)(g_acth + (size_t)row * H_);
    uint2* al = (uint2*)(g_actl + (size_t)row * H_);
    for (int i = threadIdx.x; i < H_ / 4; i += 256) {
        float4 gg = gp[i], u = gp[i + H_ / 4];
        float a[4];
        a[0] = u.x * (gg.x / (1.f + expf(-gg.x)));
        a[1] = u.y * (gg.y / (1.f + expf(-gg.y)));
        a[2] = u.z * (gg.z / (1.f + expf(-gg.z)));
        a[3] = u.w * (gg.w / (1.f + expf(-gg.w)));
        union { __half h[4]; uint2 u; } Hh, Ll;
        #pragma unroll
        for (int j = 0; j < 4; j++) splith(a[j], Hh.h[j], Ll.h[j]);
        ah[i] = Hh.u;
        al[i] = Ll.u;
    }
}

// ---------------- 8) combine ----------------
__global__ void combine_kernel(const float* __restrict__ x, float* __restrict__ out) {
    int t = blockIdx.x;
    int s0 = g_slot[2 * t], s1 = g_slot[2 * t + 1];
    float w0 = g_weight[2 * t], w1 = g_weight[2 * t + 1];
    int i = threadIdx.x;  // 192
    float4 xv = ((const float4*)(x + (size_t)t * D_))[i];
    float rx = 0.f, ry = 0.f, rz = 0.f, rw = 0.f;
    if (s0 >= 0) {
        float4 f = ((const float4*)(g_ffn + (size_t)s0 * D_))[i];
        rx += w0 * (xv.x + f.x); ry += w0 * (xv.y + f.y);
        rz += w0 * (xv.z + f.z); rw += w0 * (xv.w + f.w);
    }
    if (s1 >= 0) {
        float4 f = ((const float4*)(g_ffn + (size_t)s1 * D_))[i];
        rx += w1 * (xv.x + f.x); ry += w1 * (xv.y + f.y);
        rz += w1 * (xv.z + f.z); rw += w1 * (xv.w + f.w);
    }
    ((float4*)(out + (size_t)t * D_))[i] = make_float4(rx, ry, rz, rw);
}

// ---------------- launch (NO __device__ symbols cross the host ABI) --------
extern "C" void kernel_launch(void* const* d_in, const int* in_sizes, int n_in,
                              void* d_out, int out_size) {
    const float* x      = (const float*)d_in[0];
    const float* gate_w = (const float*)d_in[1];
    const float* w13    = (const float*)d_in[2];
    const float* w2     = (const float*)d_in[3];
    const float* norm_w = (const float*)d_in[4];
    float* out = (float*)d_out;

    rms_kernel<<<NT, 256>>>(x);
    router_kernel<<<NT / 8, 256>>>(x, gate_w);
    scan_kernel<<<E_, 256>>>();
    dispatch_kernel<<<E_ * CAP, 192>>>(norm_w);

    cvt_kernel<<<(E_ * N13 * D_) / 1024, 256>>>(w13, 0);
    cvt_kernel<<<(E_ * D_ * H_) / 1024, 256>>>(w2, 1);

    dim3 g1(N13 / 128, CAP / 128, E_);   // (32, 40, 8)
    gemm_mma<<<g1, 256>>>(0, D_, N13);

    silu_kernel<<<E_ * CAP, 256>>>();

    dim3 g2(D_ / 128, CAP / 128, E_);    // (6, 40, 8)
    gemm_mma<<<g2, 256>>>(1, H_, D_);

    combine_kernel<<<NT, 192>>>(x, out);
}

// round 8
// speedup vs baseline: 3.9904x; 1.5647x over previous
#include <cuda_runtime.h>
#include <cuda_fp16.h>
#include <math.h>
#include <stdint.h>

// ---------------- problem constants ----------------
#define NT   16384
#define NK   32768
#define D_   768
#define H_   2048
#define E_   8
#define CAP  5120
#define EPSF 1e-6f
#define N13  4096

#define RS    48        // smem row stride bytes (16 halves = 32B data + 16B pad)
#define REG   6144      // 128 rows * 48B per operand region
#define STG   12288     // A + B regions per stage

// ---------------- device scratch (referenced ONLY in device code) ----------------
__device__ float  g_xn  [(size_t)NT * D_];
__device__ __half g_zh  [(size_t)E_ * CAP * D_];
__device__ __half g_w13h[(size_t)E_ * N13 * D_];
__device__ __half g_w2h [(size_t)E_ * D_ * H_];
__device__ float  g_gu  [(size_t)E_ * CAP * 2 * H_];
__device__ __half g_acth[(size_t)E_ * CAP * H_];
__device__ float  g_ffn [(size_t)E_ * CAP * D_];
__device__ int    g_rowlist[E_ * CAP];
__device__ int    g_cnt[E_];
__device__ int    g_slot[NK];
__device__ int    g_expert[NK];
__device__ float  g_weight[NK];

// ---------------- helpers ----------------
__device__ __forceinline__ uint32_t smem_u32(const void* p) {
    uint32_t a;
    asm("{ .reg .u64 t; cvta.to.shared.u64 t, %1; cvt.u32.u64 %0, t; }" : "=r"(a) : "l"(p));
    return a;
}
__device__ __forceinline__ uint32_t lds32(uint32_t addr) {
    uint32_t v;
    asm volatile("ld.shared.b32 %0, [%1];" : "=r"(v) : "r"(addr));
    return v;
}
__device__ __forceinline__ void mma16816(float* d, const uint32_t* a, uint32_t b0, uint32_t b1) {
    asm volatile(
        "mma.sync.aligned.m16n8k16.row.col.f32.f16.f16.f32 "
        "{%0,%1,%2,%3},{%4,%5,%6,%7},{%8,%9},{%0,%1,%2,%3};"
        : "+f"(d[0]), "+f"(d[1]), "+f"(d[2]), "+f"(d[3])
        : "r"(a[0]), "r"(a[1]), "r"(a[2]), "r"(a[3]), "r"(b0), "r"(b1));
}
__device__ __forceinline__ void cp16(uint32_t saddr, const void* g) {
    asm volatile("cp.async.cg.shared.global [%0], [%1], 16;" :: "r"(saddr), "l"(g) : "memory");
}

// ---------------- 1) rmsnorm(2x) ----------------
__global__ void rms_kernel(const float* __restrict__ x) {
    int t = blockIdx.x;
    const float* xp = x + (size_t)t * D_;
    float ss = 0.f;
    for (int i = threadIdx.x; i < D_; i += 256) { float v = xp[i]; ss += v * v; }
    for (int o = 16; o; o >>= 1) ss += __shfl_xor_sync(0xffffffffu, ss, o);
    __shared__ float red[8];
    __shared__ float s_scale;
    if ((threadIdx.x & 31) == 0) red[threadIdx.x >> 5] = ss;
    __syncthreads();
    if (threadIdx.x == 0) {
        float tot = 0.f;
        #pragma unroll
        for (int j = 0; j < 8; j++) tot += red[j];
        s_scale = 2.f * rsqrtf(4.f * tot / (float)D_ + EPSF);
    }
    __syncthreads();
    float sc = s_scale;
    for (int i = threadIdx.x; i < D_; i += 256)
        g_xn[(size_t)t * D_ + i] = xp[i] * sc;
}

// ---------------- 2) router ----------------
__global__ void router_kernel(const float* __restrict__ x, const float* __restrict__ gw) {
    __shared__ float sgw[E_ * D_];
    for (int i = threadIdx.x; i < E_ * D_; i += 256) sgw[i] = gw[i];
    __syncthreads();
    int lane = threadIdx.x & 31, warp = threadIdx.x >> 5;
    int t = blockIdx.x * 8 + warp;
    const float* xp = x + (size_t)t * D_;
    float xr[24];
    #pragma unroll
    for (int j = 0; j < 24; j++) xr[j] = xp[lane + 32 * j];
    float logit[E_];
    #pragma unroll
    for (int e = 0; e < E_; e++) {
        float acc = 0.f;
        #pragma unroll
        for (int j = 0; j < 24; j++) acc += xr[j] * sgw[e * D_ + lane + 32 * j];
        for (int o = 16; o; o >>= 1) acc += __shfl_xor_sync(0xffffffffu, acc, o);
        logit[e] = acc;
    }
    if (lane == 0) {
        int i0 = 0; float l0 = logit[0];
        #pragma unroll
        for (int e = 1; e < E_; e++) if (logit[e] > l0) { l0 = logit[e]; i0 = e; }
        int i1 = -1; float l1 = -3.0e38f;
        #pragma unroll
        for (int e = 0; e < E_; e++) if (e != i0 && logit[e] > l1) { l1 = logit[e]; i1 = e; }
        float w0 = 1.f / (1.f + expf(l1 - l0));
        g_expert[2 * t]     = i0;
        g_expert[2 * t + 1] = i1;
        g_weight[2 * t]     = w0;
        g_weight[2 * t + 1] = 1.f - w0;
    }
}

// ---------------- 3) capacity scan ----------------
__global__ void scan_kernel() {
    int e = blockIdx.x;
    int tid = threadIdx.x;
    __shared__ int warpsum[8];
    __shared__ int sbase;
    if (tid == 0) sbase = 0;
    __syncthreads();
    for (int i0 = 0; i0 < NK; i0 += 256) {
        int i = i0 + tid;
        int mine = (g_expert[i] == e) ? 1 : 0;
        unsigned m = __ballot_sync(0xffffffffu, mine);
        int lane = tid & 31, w = tid >> 5;
        if (lane == 0) warpsum[w] = __popc(m);
        __syncthreads();
        int off = 0, tot = 0;
        #pragma unroll
        for (int j = 0; j < 8; j++) { int c = warpsum[j]; tot += c; if (j < w) off += c; }
        int rank = sbase + off + __popc(m & ((1u << lane) - 1u));
        if (mine) {
            if (rank < CAP) { g_rowlist[e * CAP + rank] = i; g_slot[i] = e * CAP + rank; }
            else            { g_slot[i] = -1; }
        }
        __syncthreads();
        if (tid == 0) sbase += tot;
    }
    __syncthreads();
    if (tid == 0) g_cnt[e] = (sbase < CAP) ? sbase : CAP;
}

// ---------------- 4) dispatch -> fp16 ----------------
__global__ void dispatch_kernel(const float* __restrict__ norm_w) {
    int slot = blockIdx.x;
    int e = slot / CAP, r = slot % CAP;
    if (r >= g_cnt[e]) return;
    int t = g_rowlist[slot] >> 1;
    int i = threadIdx.x;  // 192 threads * 4 = 768
    float4 a = ((const float4*)(g_xn + (size_t)t * D_))[i];
    float4 b = ((const float4*)(norm_w + (size_t)e * D_))[i];
    union { __half h[4]; uint2 u; } Hh;
    Hh.h[0] = __float2half_rn(a.x * b.x);
    Hh.h[1] = __float2half_rn(a.y * b.y);
    Hh.h[2] = __float2half_rn(a.z * b.z);
    Hh.h[3] = __float2half_rn(a.w * b.w);
    ((uint2*)(g_zh + (size_t)slot * D_))[i] = Hh.u;
}

// ---------------- weights fp32 -> fp16 (dst selected in DEVICE code) -------
__global__ void cvt_kernel(const float* __restrict__ src, int which) {
    __half* dst = which ? g_w2h : g_w13h;
    int i = blockIdx.x * 256 + threadIdx.x;
    float4 v = ((const float4*)src)[i];
    union { __half h[4]; uint2 u; } H;
    H.h[0] = __float2half_rn(v.x); H.h[1] = __float2half_rn(v.y);
    H.h[2] = __float2half_rn(v.z); H.h[3] = __float2half_rn(v.w);
    ((uint2*)dst)[i] = H.u;
}

// ---------------- grouped GEMM via mma.sync (pure fp16, 3-stage pipeline) ----
// C[m,n] = sum_k A[m,k]*B[n,k]. Tile 128x128, KCH=16, one barrier per chunk.
__global__ __launch_bounds__(256) void gemm_mma(int which, int K, int Ntot)
{
    __shared__ __align__(16) char sm[3][STG];

    const __half* Ahg = which ? g_acth : g_zh;
    const __half* Bg  = which ? g_w2h  : g_w13h;
    float*        Cg  = which ? g_ffn  : g_gu;

    int e = blockIdx.z;
    int m0 = blockIdx.y * 128;
    if (m0 >= g_cnt[e]) return;
    int n0 = blockIdx.x * 128;

    int tid = threadIdx.x, lane = tid & 31, wid = tid >> 5;
    int wm = wid & 1, wn = wid >> 1;           // 2x4 warp grid, warp tile 64x32
    int g = lane >> 2, q = lane & 3;

    const __half* pA = Ahg + ((size_t)e * CAP + m0) * K;
    const __half* pB = Bg  + ((size_t)e * Ntot + n0) * K;

    float acc[4][4][4];
    #pragma unroll
    for (int i = 0; i < 4; i++)
        #pragma unroll
        for (int j = 0; j < 4; j++)
            #pragma unroll
            for (int p = 0; p < 4; p++) acc[i][j][p] = 0.f;

    int row_ld = tid >> 1, half_ld = tid & 1;            // 256 threads: 128 rows x 2 chunks
    uint32_t soff_ld = (uint32_t)row_ld * RS + (uint32_t)half_ld * 16;
    size_t goff_base = (size_t)row_ld * K + half_ld * 8;

    int NCH = K >> 4;

    // prologue: stages 0,1
    #pragma unroll
    for (int c = 0; c < 2; c++) {
        uint32_t sb = smem_u32(sm[c]);
        size_t go = goff_base + c * 16;
        cp16(sb + soff_ld,       pA + go);
        cp16(sb + REG + soff_ld, pB + go);
        asm volatile("cp.async.commit_group;" ::: "memory");
    }

    int stage = 0, pstage = 2;
    for (int c = 0; c < NCH; c++) {
        asm volatile("cp.async.wait_group %0;" :: "n"(1) : "memory");
        __syncthreads();

        // prefetch chunk c+2 into stage (c+2)%3 — its previous readers passed the barrier
        if (c + 2 < NCH) {
            uint32_t sbp = smem_u32(sm[pstage]);
            size_t go = goff_base + (size_t)(c + 2) * 16;
            cp16(sbp + soff_ld,       pA + go);
            cp16(sbp + REG + soff_ld, pB + go);
        }
        asm volatile("cp.async.commit_group;" ::: "memory");

        uint32_t sb = smem_u32(sm[stage]);
        uint32_t kb = (uint32_t)q * 4;       // byte offset of the thread's k-pair

        // B fragments: n = wn*32 + nf*8 + g ; b0 = k[2q..2q+1], b1 = k[2q+8..]
        uint32_t bfr[4][2];
        #pragma unroll
        for (int nf = 0; nf < 4; nf++) {
            uint32_t bo = sb + REG + (uint32_t)(wn * 32 + nf * 8 + g) * RS + kb;
            bfr[nf][0] = lds32(bo);
            bfr[nf][1] = lds32(bo + 16);
        }
        #pragma unroll
        for (int mf = 0; mf < 4; mf++) {
            uint32_t ao = sb + (uint32_t)(wm * 64 + mf * 16 + g) * RS + kb;
            uint32_t ah[4];
            ah[0] = lds32(ao);
            ah[1] = lds32(ao + 8 * RS);
            ah[2] = lds32(ao + 16);
            ah[3] = lds32(ao + 8 * RS + 16);
            #pragma unroll
            for (int nf = 0; nf < 4; nf++)
                mma16816(acc[mf][nf], ah, bfr[nf][0], bfr[nf][1]);
        }
        stage = (stage == 2) ? 0 : stage + 1;
        pstage = (pstage == 2) ? 0 : pstage + 1;
    }

    float* C = Cg + ((size_t)e * CAP + m0) * Ntot + n0;
    #pragma unroll
    for (int mf = 0; mf < 4; mf++)
        #pragma unroll
        for (int nf = 0; nf < 4; nf++) {
            int r0 = wm * 64 + mf * 16 + g;
            int col = wn * 32 + nf * 8 + q * 2;
            *(float2*)(C + (size_t)r0 * Ntot + col) =
                make_float2(acc[mf][nf][0], acc[mf][nf][1]);
            *(float2*)(C + (size_t)(r0 + 8) * Ntot + col) =
                make_float2(acc[mf][nf][2], acc[mf][nf][3]);
        }
}

// ---------------- 6) silu -> act fp16 ----------------
__global__ void silu_kernel() {
    int row = blockIdx.x;
    int e = row / CAP;
    if (row % CAP >= g_cnt[e]) return;
    const float4* gp = (const float4*)(g_gu + (size_t)row * 2 * H_);
    uint2* ah = (uint2*)(g_acth + (size_t)row * H_);
    for (int i = threadIdx.x; i < H_ / 4; i += 256) {
        float4 gg = gp[i], u = gp[i + H_ / 4];
        union { __half h[4]; uint2 u; } Hh;
        Hh.h[0] = __float2half_rn(u.x * (gg.x / (1.f + expf(-gg.x))));
        Hh.h[1] = __float2half_rn(u.y * (gg.y / (1.f + expf(-gg.y))));
        Hh.h[2] = __float2half_rn(u.z * (gg.z / (1.f + expf(-gg.z))));
        Hh.h[3] = __float2half_rn(u.w * (gg.w / (1.f + expf(-gg.w))));
        ah[i] = Hh.u;
    }
}

// ---------------- 8) combine ----------------
__global__ void combine_kernel(const float* __restrict__ x, float* __restrict__ out) {
    int t = blockIdx.x;
    int s0 = g_slot[2 * t], s1 = g_slot[2 * t + 1];
    float w0 = g_weight[2 * t], w1 = g_weight[2 * t + 1];
    int i = threadIdx.x;  // 192
    float4 xv = ((const float4*)(x + (size_t)t * D_))[i];
    float rx = 0.f, ry = 0.f, rz = 0.f, rw = 0.f;
    if (s0 >= 0) {
        float4 f = ((const float4*)(g_ffn + (size_t)s0 * D_))[i];
        rx += w0 * (xv.x + f.x); ry += w0 * (xv.y + f.y);
        rz += w0 * (xv.z + f.z); rw += w0 * (xv.w + f.w);
    }
    if (s1 >= 0) {
        float4 f = ((const float4*)(g_ffn + (size_t)s1 * D_))[i];
        rx += w1 * (xv.x + f.x); ry += w1 * (xv.y + f.y);
        rz += w1 * (xv.z + f.z); rw += w1 * (xv.w + f.w);
    }
    ((float4*)(out + (size_t)t * D_))[i] = make_float4(rx, ry, rz, rw);
}

// ---------------- launch (NO __device__ symbols cross the host ABI) --------
extern "C" void kernel_launch(void* const* d_in, const int* in_sizes, int n_in,
                              void* d_out, int out_size) {
    const float* x      = (const float*)d_in[0];
    const float* gate_w = (const float*)d_in[1];
    const float* w13    = (const float*)d_in[2];
    const float* w2     = (const float*)d_in[3];
    const float* norm_w = (const float*)d_in[4];
    float* out = (float*)d_out;

    rms_kernel<<<NT, 256>>>(x);
    router_kernel<<<NT / 8, 256>>>(x, gate_w);
    scan_kernel<<<E_, 256>>>();
    dispatch_kernel<<<E_ * CAP, 192>>>(norm_w);

    cvt_kernel<<<(E_ * N13 * D_) / 1024, 256>>>(w13, 0);
    cvt_kernel<<<(E_ * D_ * H_) / 1024, 256>>>(w2, 1);

    dim3 g1(N13 / 128, CAP / 128, E_);   // (32, 40, 8)
    gemm_mma<<<g1, 256>>>(0, D_, N13);

    silu_kernel<<<E_ * CAP, 256>>>();

    dim3 g2(D_ / 128, CAP / 128, E_);    // (6, 40, 8)
    gemm_mma<<<g2, 256>>>(1, H_, D_);

    combine_kernel<<<NT, 192>>>(x, out);
}

// round 9
// speedup vs baseline: 4.3843x; 1.0987x over previous
#include <cuda_runtime.h>
#include <cuda_fp16.h>
#include <math.h>
#include <stdint.h>

// ---------------- problem constants ----------------
#define NT   16384
#define NK   32768
#define D_   768
#define H_   2048
#define E_   8
#define CAP  5120
#define EPSF 1e-6f
#define N13  4096

#define RS    48        // smem row stride bytes (16 halves = 32B data + 16B pad)
#define REG   6144      // 128 rows * 48B per operand region
#define STG1  18432     // gemm1: A + Bg + Bu
#define STG2  12288     // gemm2: A + B

// ---------------- device scratch (referenced ONLY in device code) ----------------
__device__ float  g_scale[NT];                        // rms scale per token
__device__ __half g_zh  [(size_t)E_ * CAP * D_];
__device__ __half g_w13h[(size_t)E_ * N13 * D_];
__device__ __half g_w2h [(size_t)E_ * D_ * H_];
__device__ __half g_acth[(size_t)E_ * CAP * H_];
__device__ float  g_ffn [(size_t)E_ * CAP * D_];
__device__ int    g_rowlist[E_ * CAP];
__device__ int    g_cnt[E_];
__device__ int    g_slot[NK];
__device__ int    g_expert[NK];
__device__ float  g_weight[NK];

// ---------------- helpers ----------------
__device__ __forceinline__ uint32_t smem_u32(const void* p) {
    uint32_t a;
    asm("{ .reg .u64 t; cvta.to.shared.u64 t, %1; cvt.u32.u64 %0, t; }" : "=r"(a) : "l"(p));
    return a;
}
__device__ __forceinline__ uint32_t lds32(uint32_t addr) {
    uint32_t v;
    asm volatile("ld.shared.b32 %0, [%1];" : "=r"(v) : "r"(addr));
    return v;
}
__device__ __forceinline__ void mma16816(float* d, const uint32_t* a, uint32_t b0, uint32_t b1) {
    asm volatile(
        "mma.sync.aligned.m16n8k16.row.col.f32.f16.f16.f32 "
        "{%0,%1,%2,%3},{%4,%5,%6,%7},{%8,%9},{%0,%1,%2,%3};"
        : "+f"(d[0]), "+f"(d[1]), "+f"(d[2]), "+f"(d[3])
        : "r"(a[0]), "r"(a[1]), "r"(a[2]), "r"(a[3]), "r"(b0), "r"(b1));
}
__device__ __forceinline__ void cp16(uint32_t saddr, const void* g) {
    asm volatile("cp.async.cg.shared.global [%0], [%1], 16;" :: "r"(saddr), "l"(g) : "memory");
}
__device__ __forceinline__ float silu_mul(float g, float u) {
    return u * (g / (1.f + expf(-g)));
}

// ---------------- 1) router + fused rms scale ----------------
__global__ void router_kernel(const float* __restrict__ x, const float* __restrict__ gw) {
    __shared__ float sgw[E_ * D_];
    for (int i = threadIdx.x; i < E_ * D_; i += 256) sgw[i] = gw[i];
    __syncthreads();
    int lane = threadIdx.x & 31, warp = threadIdx.x >> 5;
    int t = blockIdx.x * 8 + warp;
    const float* xp = x + (size_t)t * D_;
    float xr[24];
    float ss = 0.f;
    #pragma unroll
    for (int j = 0; j < 24; j++) { xr[j] = xp[lane + 32 * j]; ss += xr[j] * xr[j]; }
    for (int o = 16; o; o >>= 1) ss += __shfl_xor_sync(0xffffffffu, ss, o);
    float logit[E_];
    #pragma unroll
    for (int e = 0; e < E_; e++) {
        float acc = 0.f;
        #pragma unroll
        for (int j = 0; j < 24; j++) acc += xr[j] * sgw[e * D_ + lane + 32 * j];
        for (int o = 16; o; o >>= 1) acc += __shfl_xor_sync(0xffffffffu, acc, o);
        logit[e] = acc;
    }
    if (lane == 0) {
        // rms scale for z = 2x: 2*rsqrt(4*sum/D + eps)
        g_scale[t] = 2.f * rsqrtf(4.f * ss / (float)D_ + EPSF);
        int i0 = 0; float l0 = logit[0];
        #pragma unroll
        for (int e = 1; e < E_; e++) if (logit[e] > l0) { l0 = logit[e]; i0 = e; }
        int i1 = -1; float l1 = -3.0e38f;
        #pragma unroll
        for (int e = 0; e < E_; e++) if (e != i0 && logit[e] > l1) { l1 = logit[e]; i1 = e; }
        float w0 = 1.f / (1.f + expf(l1 - l0));
        g_expert[2 * t]     = i0;
        g_expert[2 * t + 1] = i1;
        g_weight[2 * t]     = w0;
        g_weight[2 * t + 1] = 1.f - w0;
    }
}

// ---------------- 2) capacity scan ----------------
__global__ void scan_kernel() {
    int e = blockIdx.x;
    int tid = threadIdx.x;
    __shared__ int warpsum[8];
    __shared__ int sbase;
    if (tid == 0) sbase = 0;
    __syncthreads();
    for (int i0 = 0; i0 < NK; i0 += 256) {
        int i = i0 + tid;
        int mine = (g_expert[i] == e) ? 1 : 0;
        unsigned m = __ballot_sync(0xffffffffu, mine);
        int lane = tid & 31, w = tid >> 5;
        if (lane == 0) warpsum[w] = __popc(m);
        __syncthreads();
        int off = 0, tot = 0;
        #pragma unroll
        for (int j = 0; j < 8; j++) { int c = warpsum[j]; tot += c; if (j < w) off += c; }
        int rank = sbase + off + __popc(m & ((1u << lane) - 1u));
        if (mine) {
            if (rank < CAP) { g_rowlist[e * CAP + rank] = i; g_slot[i] = e * CAP + rank; }
            else            { g_slot[i] = -1; }
        }
        __syncthreads();
        if (tid == 0) sbase += tot;
    }
    __syncthreads();
    if (tid == 0) g_cnt[e] = (sbase < CAP) ? sbase : CAP;
}

// ---------------- 3) dispatch -> fp16 (reads x directly with scale) ---------
__global__ void dispatch_kernel(const float* __restrict__ x, const float* __restrict__ norm_w) {
    int slot = blockIdx.x;
    int e = slot / CAP, r = slot % CAP;
    if (r >= g_cnt[e]) return;
    int t = g_rowlist[slot] >> 1;
    float sc = g_scale[t];
    int i = threadIdx.x;  // 192 threads * 4 = 768
    float4 a = ((const float4*)(x + (size_t)t * D_))[i];
    float4 b = ((const float4*)(norm_w + (size_t)e * D_))[i];
    union { __half h[4]; uint2 u; } Hh;
    Hh.h[0] = __float2half_rn(a.x * sc * b.x);
    Hh.h[1] = __float2half_rn(a.y * sc * b.y);
    Hh.h[2] = __float2half_rn(a.z * sc * b.z);
    Hh.h[3] = __float2half_rn(a.w * sc * b.w);
    ((uint2*)(g_zh + (size_t)slot * D_))[i] = Hh.u;
}

// ---------------- weights fp32 -> fp16 (dst selected in DEVICE code) -------
__global__ void cvt_kernel(const float* __restrict__ src, int which) {
    __half* dst = which ? g_w2h : g_w13h;
    int i = blockIdx.x * 256 + threadIdx.x;
    float4 v = ((const float4*)src)[i];
    union { __half h[4]; uint2 u; } H;
    H.h[0] = __float2half_rn(v.x); H.h[1] = __float2half_rn(v.y);
    H.h[2] = __float2half_rn(v.z); H.h[3] = __float2half_rn(v.w);
    ((uint2*)dst)[i] = H.u;
}

// ---------------- 4) GEMM1 fused with silu: acth = silu(z@Wg^T) * (z@Wu^T) --
// Each block: M-tile 128, and BOTH N-tiles n0 (gate) and n0+2048 (up).
// 2-stage double buffer, KCH=16, two barriers per chunk.
__global__ __launch_bounds__(256) void gemm1_silu()
{
    __shared__ __align__(16) char sm[2][STG1];

    int e = blockIdx.z;
    int m0 = blockIdx.y * 128;
    if (m0 >= g_cnt[e]) return;
    int n0 = blockIdx.x * 128;

    int tid = threadIdx.x, lane = tid & 31, wid = tid >> 5;
    int wm = wid & 1, wn = wid >> 1;
    int g = lane >> 2, q = lane & 3;

    const __half* pA  = g_zh   + ((size_t)e * CAP + m0) * D_;
    const __half* pBg = g_w13h + ((size_t)e * N13 + n0) * D_;
    const __half* pBu = g_w13h + ((size_t)e * N13 + H_ + n0) * D_;

    float accg[4][4][4], accu[4][4][4];
    #pragma unroll
    for (int i = 0; i < 4; i++)
        #pragma unroll
        for (int j = 0; j < 4; j++)
            #pragma unroll
            for (int p = 0; p < 4; p++) { accg[i][j][p] = 0.f; accu[i][j][p] = 0.f; }

    int r_ld = tid >> 1, h_ld = tid & 1;
    uint32_t soff = (uint32_t)r_ld * RS + (uint32_t)h_ld * 16;
    size_t gbase = (size_t)r_ld * D_ + h_ld * 8;

    const int NCH = D_ >> 4;   // 48

    #pragma unroll
    for (int c = 0; c < 2; c++) {
        uint32_t sb = smem_u32(sm[c]);
        size_t go = gbase + c * 16;
        cp16(sb + soff,           pA  + go);
        cp16(sb + REG + soff,     pBg + go);
        cp16(sb + 2 * REG + soff, pBu + go);
        asm volatile("cp.async.commit_group;" ::: "memory");
    }

    for (int c = 0; c < NCH; c++) {
        asm volatile("cp.async.wait_group %0;" :: "n"(1) : "memory");
        __syncthreads();

        uint32_t sb = smem_u32(sm[c & 1]);
        uint32_t kb = (uint32_t)q * 4;

        uint32_t bgf[4][2], buf[4][2];
        #pragma unroll
        for (int nf = 0; nf < 4; nf++) {
            uint32_t ro = (uint32_t)(wn * 32 + nf * 8 + g) * RS + kb;
            bgf[nf][0] = lds32(sb + REG + ro);
            bgf[nf][1] = lds32(sb + REG + ro + 16);
            buf[nf][0] = lds32(sb + 2 * REG + ro);
            buf[nf][1] = lds32(sb + 2 * REG + ro + 16);
        }
        #pragma unroll
        for (int mf = 0; mf < 4; mf++) {
            uint32_t ao = sb + (uint32_t)(wm * 64 + mf * 16 + g) * RS + kb;
            uint32_t ah[4];
            ah[0] = lds32(ao);
            ah[1] = lds32(ao + 8 * RS);
            ah[2] = lds32(ao + 16);
            ah[3] = lds32(ao + 8 * RS + 16);
            #pragma unroll
            for (int nf = 0; nf < 4; nf++) {
                mma16816(accg[mf][nf], ah, bgf[nf][0], bgf[nf][1]);
                mma16816(accu[mf][nf], ah, buf[nf][0], buf[nf][1]);
            }
        }
        __syncthreads();
        if (c + 2 < NCH) {
            uint32_t sb2 = smem_u32(sm[c & 1]);
            size_t go = gbase + (size_t)(c + 2) * 16;
            cp16(sb2 + soff,           pA  + go);
            cp16(sb2 + REG + soff,     pBg + go);
            cp16(sb2 + 2 * REG + soff, pBu + go);
        }
        asm volatile("cp.async.commit_group;" ::: "memory");
    }

    __half* Ca = g_acth + ((size_t)e * CAP + m0) * H_ + n0;
    #pragma unroll
    for (int mf = 0; mf < 4; mf++)
        #pragma unroll
        for (int nf = 0; nf < 4; nf++) {
            int r0 = wm * 64 + mf * 16 + g;
            int col = wn * 32 + nf * 8 + q * 2;
            float a0 = silu_mul(accg[mf][nf][0], accu[mf][nf][0]);
            float a1 = silu_mul(accg[mf][nf][1], accu[mf][nf][1]);
            float a2 = silu_mul(accg[mf][nf][2], accu[mf][nf][2]);
            float a3 = silu_mul(accg[mf][nf][3], accu[mf][nf][3]);
            *(__half2*)(Ca + (size_t)r0 * H_ + col)       = __floats2half2_rn(a0, a1);
            *(__half2*)(Ca + (size_t)(r0 + 8) * H_ + col) = __floats2half2_rn(a2, a3);
        }
}

// ---------------- 5) GEMM2: ffn = act @ W2^T  (3-stage pipeline) -----------
__global__ __launch_bounds__(256) void gemm2_mma()
{
    __shared__ __align__(16) char sm[3][STG2];

    const int K = H_, Ntot = D_;
    int e = blockIdx.z;
    int m0 = blockIdx.y * 128;
    if (m0 >= g_cnt[e]) return;
    int n0 = blockIdx.x * 128;

    int tid = threadIdx.x, lane = tid & 31, wid = tid >> 5;
    int wm = wid & 1, wn = wid >> 1;
    int g = lane >> 2, q = lane & 3;

    const __half* pA = g_acth + ((size_t)e * CAP + m0) * K;
    const __half* pB = g_w2h  + ((size_t)e * Ntot + n0) * K;

    float acc[4][4][4];
    #pragma unroll
    for (int i = 0; i < 4; i++)
        #pragma unroll
        for (int j = 0; j < 4; j++)
            #pragma unroll
            for (int p = 0; p < 4; p++) acc[i][j][p] = 0.f;

    int r_ld = tid >> 1, h_ld = tid & 1;
    uint32_t soff = (uint32_t)r_ld * RS + (uint32_t)h_ld * 16;
    size_t gbase = (size_t)r_ld * K + h_ld * 8;

    const int NCH = K >> 4;   // 128

    #pragma unroll
    for (int c = 0; c < 2; c++) {
        uint32_t sb = smem_u32(sm[c]);
        size_t go = gbase + c * 16;
        cp16(sb + soff,       pA + go);
        cp16(sb + REG + soff, pB + go);
        asm volatile("cp.async.commit_group;" ::: "memory");
    }

    int stage = 0, pstage = 2;
    for (int c = 0; c < NCH; c++) {
        asm volatile("cp.async.wait_group %0;" :: "n"(1) : "memory");
        __syncthreads();

        if (c + 2 < NCH) {
            uint32_t sbp = smem_u32(sm[pstage]);
            size_t go = gbase + (size_t)(c + 2) * 16;
            cp16(sbp + soff,       pA + go);
            cp16(sbp + REG + soff, pB + go);
        }
        asm volatile("cp.async.commit_group;" ::: "memory");

        uint32_t sb = smem_u32(sm[stage]);
        uint32_t kb = (uint32_t)q * 4;

        uint32_t bfr[4][2];
        #pragma unroll
        for (int nf = 0; nf < 4; nf++) {
            uint32_t bo = sb + REG + (uint32_t)(wn * 32 + nf * 8 + g) * RS + kb;
            bfr[nf][0] = lds32(bo);
            bfr[nf][1] = lds32(bo + 16);
        }
        #pragma unroll
        for (int mf = 0; mf < 4; mf++) {
            uint32_t ao = sb + (uint32_t)(wm * 64 + mf * 16 + g) * RS + kb;
            uint32_t ah[4];
            ah[0] = lds32(ao);
            ah[1] = lds32(ao + 8 * RS);
            ah[2] = lds32(ao + 16);
            ah[3] = lds32(ao + 8 * RS + 16);
            #pragma unroll
            for (int nf = 0; nf < 4; nf++)
                mma16816(acc[mf][nf], ah, bfr[nf][0], bfr[nf][1]);
        }
        stage = (stage == 2) ? 0 : stage + 1;
        pstage = (pstage == 2) ? 0 : pstage + 1;
    }

    float* C = g_ffn + ((size_t)e * CAP + m0) * Ntot + n0;
    #pragma unroll
    for (int mf = 0; mf < 4; mf++)
        #pragma unroll
        for (int nf = 0; nf < 4; nf++) {
            int r0 = wm * 64 + mf * 16 + g;
            int col = wn * 32 + nf * 8 + q * 2;
            *(float2*)(C + (size_t)r0 * Ntot + col) =
                make_float2(acc[mf][nf][0], acc[mf][nf][1]);
            *(float2*)(C + (size_t)(r0 + 8) * Ntot + col) =
                make_float2(acc[mf][nf][2], acc[mf][nf][3]);
        }
}

// ---------------- 6) combine ----------------
__global__ void combine_kernel(const float* __restrict__ x, float* __restrict__ out) {
    int t = blockIdx.x;
    int s0 = g_slot[2 * t], s1 = g_slot[2 * t + 1];
    float w0 = g_weight[2 * t], w1 = g_weight[2 * t + 1];
    int i = threadIdx.x;  // 192
    float4 xv = ((const float4*)(x + (size_t)t * D_))[i];
    float rx = 0.f, ry = 0.f, rz = 0.f, rw = 0.f;
    if (s0 >= 0) {
        float4 f = ((const float4*)(g_ffn + (size_t)s0 * D_))[i];
        rx += w0 * (xv.x + f.x); ry += w0 * (xv.y + f.y);
        rz += w0 * (xv.z + f.z); rw += w0 * (xv.w + f.w);
    }
    if (s1 >= 0) {
        float4 f = ((const float4*)(g_ffn + (size_t)s1 * D_))[i];
        rx += w1 * (xv.x + f.x); ry += w1 * (xv.y + f.y);
        rz += w1 * (xv.z + f.z); rw += w1 * (xv.w + f.w);
    }
    ((float4*)(out + (size_t)t * D_))[i] = make_float4(rx, ry, rz, rw);
}

// ---------------- launch (NO __device__ symbols cross the host ABI) --------
extern "C" void kernel_launch(void* const* d_in, const int* in_sizes, int n_in,
                              void* d_out, int out_size) {
    const float* x      = (const float*)d_in[0];
    const float* gate_w = (const float*)d_in[1];
    const float* w13    = (const float*)d_in[2];
    const float* w2     = (const float*)d_in[3];
    const float* norm_w = (const float*)d_in[4];
    float* out = (float*)d_out;

    router_kernel<<<NT / 8, 256>>>(x, gate_w);
    scan_kernel<<<E_, 256>>>();
    dispatch_kernel<<<E_ * CAP, 192>>>(x, norm_w);

    cvt_kernel<<<(E_ * N13 * D_) / 1024, 256>>>(w13, 0);
    cvt_kernel<<<(E_ * D_ * H_) / 1024, 256>>>(w2, 1);

    dim3 g1(H_ / 128, CAP / 128, E_);    // (16, 40, 8): dual-tile gate+up
    gemm1_silu<<<g1, 256>>>();

    dim3 g2(D_ / 128, CAP / 128, E_);    // (6, 40, 8)
    gemm2_mma<<<g2, 256>>>();

    combine_kernel<<<NT, 192>>>(x, out);
}

// round 10
// speedup vs baseline: 5.2695x; 1.2019x over previous
#include <cuda_runtime.h>
#include <cuda_fp16.h>
#include <math.h>
#include <stdint.h>

// ---------------- problem constants ----------------
#define NT   16384
#define NK   32768
#define D_   768
#define H_   2048
#define E_   8
#define CAP  5120
#define EPSF 1e-6f
#define N13  4096

#define ROWB 32          // bytes per smem row (16 halves, no pad; XOR swizzle)
#define RGN  4096        // 128 rows * 32B per operand region
#define STG1 12288       // gemm1 stage: A + Bg + Bu
#define STG2 8192        // gemm2 stage: A + B

// ---------------- device scratch (referenced ONLY in device code) ----------------
__device__ float  g_scale[NT];
__device__ __half g_zh  [(size_t)E_ * CAP * D_];
__device__ __half g_w13h[(size_t)E_ * N13 * D_];
__device__ __half g_w2h [(size_t)E_ * D_ * H_];
__device__ __half g_acth[(size_t)E_ * CAP * H_];
__device__ float  g_ffn [(size_t)E_ * CAP * D_];
__device__ int    g_rowlist[E_ * CAP];
__device__ int    g_cnt[E_];
__device__ int    g_slot[NK];
__device__ int    g_expert[NK];
__device__ float  g_weight[NK];

// ---------------- helpers ----------------
__device__ __forceinline__ uint32_t smem_u32(const void* p) {
    uint32_t a;
    asm("{ .reg .u64 t; cvta.to.shared.u64 t, %1; cvt.u32.u64 %0, t; }" : "=r"(a) : "l"(p));
    return a;
}
__device__ __forceinline__ void ldsm4(uint32_t& r0, uint32_t& r1, uint32_t& r2, uint32_t& r3,
                                      uint32_t addr) {
    asm volatile("ldmatrix.sync.aligned.m8n8.x4.shared.b16 {%0,%1,%2,%3}, [%4];"
                 : "=r"(r0), "=r"(r1), "=r"(r2), "=r"(r3) : "r"(addr));
}
__device__ __forceinline__ void mma16816(float* d, const uint32_t* a, uint32_t b0, uint32_t b1) {
    asm volatile(
        "mma.sync.aligned.m16n8k16.row.col.f32.f16.f16.f32 "
        "{%0,%1,%2,%3},{%4,%5,%6,%7},{%8,%9},{%0,%1,%2,%3};"
        : "+f"(d[0]), "+f"(d[1]), "+f"(d[2]), "+f"(d[3])
        : "r"(a[0]), "r"(a[1]), "r"(a[2]), "r"(a[3]), "r"(b0), "r"(b1));
}
__device__ __forceinline__ void cp16(uint32_t saddr, const void* g) {
    asm volatile("cp.async.cg.shared.global [%0], [%1], 16;" :: "r"(saddr), "l"(g) : "memory");
}
__device__ __forceinline__ float silu_mul(float g, float u) {
    return u * (g / (1.f + expf(-g)));
}
// swizzled smem byte offset for (row, 16B-chunk)
__device__ __forceinline__ uint32_t swz(int row, int ch) {
    return (uint32_t)row * ROWB + (uint32_t)((ch ^ ((row >> 2) & 1)) << 4);
}

// ---------------- 1) router + fused rms scale ----------------
__global__ void router_kernel(const float* __restrict__ x, const float* __restrict__ gw) {
    __shared__ float sgw[E_ * D_];
    for (int i = threadIdx.x; i < E_ * D_; i += 256) sgw[i] = gw[i];
    __syncthreads();
    int lane = threadIdx.x & 31, warp = threadIdx.x >> 5;
    int t = blockIdx.x * 8 + warp;
    const float* xp = x + (size_t)t * D_;
    float xr[24];
    float ss = 0.f;
    #pragma unroll
    for (int j = 0; j < 24; j++) { xr[j] = xp[lane + 32 * j]; ss += xr[j] * xr[j]; }
    for (int o = 16; o; o >>= 1) ss += __shfl_xor_sync(0xffffffffu, ss, o);
    float logit[E_];
    #pragma unroll
    for (int e = 0; e < E_; e++) {
        float acc = 0.f;
        #pragma unroll
        for (int j = 0; j < 24; j++) acc += xr[j] * sgw[e * D_ + lane + 32 * j];
        for (int o = 16; o; o >>= 1) acc += __shfl_xor_sync(0xffffffffu, acc, o);
        logit[e] = acc;
    }
    if (lane == 0) {
        g_scale[t] = 2.f * rsqrtf(4.f * ss / (float)D_ + EPSF);
        int i0 = 0; float l0 = logit[0];
        #pragma unroll
        for (int e = 1; e < E_; e++) if (logit[e] > l0) { l0 = logit[e]; i0 = e; }
        int i1 = -1; float l1 = -3.0e38f;
        #pragma unroll
        for (int e = 0; e < E_; e++) if (e != i0 && logit[e] > l1) { l1 = logit[e]; i1 = e; }
        float w0 = 1.f / (1.f + expf(l1 - l0));
        g_expert[2 * t]     = i0;
        g_expert[2 * t + 1] = i1;
        g_weight[2 * t]     = w0;
        g_weight[2 * t + 1] = 1.f - w0;
    }
}

// ---------------- 2) capacity scan ----------------
__global__ void scan_kernel() {
    int e = blockIdx.x;
    int tid = threadIdx.x;
    __shared__ int warpsum[8];
    __shared__ int sbase;
    if (tid == 0) sbase = 0;
    __syncthreads();
    for (int i0 = 0; i0 < NK; i0 += 256) {
        int i = i0 + tid;
        int mine = (g_expert[i] == e) ? 1 : 0;
        unsigned m = __ballot_sync(0xffffffffu, mine);
        int lane = tid & 31, w = tid >> 5;
        if (lane == 0) warpsum[w] = __popc(m);
        __syncthreads();
        int off = 0, tot = 0;
        #pragma unroll
        for (int j = 0; j < 8; j++) { int c = warpsum[j]; tot += c; if (j < w) off += c; }
        int rank = sbase + off + __popc(m & ((1u << lane) - 1u));
        if (mine) {
            if (rank < CAP) { g_rowlist[e * CAP + rank] = i; g_slot[i] = e * CAP + rank; }
            else            { g_slot[i] = -1; }
        }
        __syncthreads();
        if (tid == 0) sbase += tot;
    }
    __syncthreads();
    if (tid == 0) g_cnt[e] = (sbase < CAP) ? sbase : CAP;
}

// ---------------- 3) dispatch -> fp16 ----------------
__global__ void dispatch_kernel(const float* __restrict__ x, const float* __restrict__ norm_w) {
    int slot = blockIdx.x;
    int e = slot / CAP, r = slot % CAP;
    if (r >= g_cnt[e]) return;
    int t = g_rowlist[slot] >> 1;
    float sc = g_scale[t];
    int i = threadIdx.x;  // 192 threads * 4 = 768
    float4 a = ((const float4*)(x + (size_t)t * D_))[i];
    float4 b = ((const float4*)(norm_w + (size_t)e * D_))[i];
    union { __half h[4]; uint2 u; } Hh;
    Hh.h[0] = __float2half_rn(a.x * sc * b.x);
    Hh.h[1] = __float2half_rn(a.y * sc * b.y);
    Hh.h[2] = __float2half_rn(a.z * sc * b.z);
    Hh.h[3] = __float2half_rn(a.w * sc * b.w);
    ((uint2*)(g_zh + (size_t)slot * D_))[i] = Hh.u;
}

// ---------------- weights fp32 -> fp16 ----------------
__global__ void cvt_kernel(const float* __restrict__ src, int which) {
    __half* dst = which ? g_w2h : g_w13h;
    int i = blockIdx.x * 256 + threadIdx.x;
    float4 v = ((const float4*)src)[i];
    union { __half h[4]; uint2 u; } H;
    H.h[0] = __float2half_rn(v.x); H.h[1] = __float2half_rn(v.y);
    H.h[2] = __float2half_rn(v.z); H.h[3] = __float2half_rn(v.w);
    ((uint2*)dst)[i] = H.u;
}

// ---------------- 4) GEMM1 fused with silu (ldmatrix, 3-stage) -------------
__global__ __launch_bounds__(256) void gemm1_silu()
{
    __shared__ __align__(16) char sm[3][STG1];

    int e = blockIdx.z;
    int m0 = blockIdx.y * 128;
    if (m0 >= g_cnt[e]) return;
    int n0 = blockIdx.x * 128;

    int tid = threadIdx.x, lane = tid & 31, wid = tid >> 5;
    int wm = wid & 1, wn = wid >> 1;
    int g = lane >> 2, q = lane & 3;

    const __half* pA  = g_zh   + ((size_t)e * CAP + m0) * D_;
    const __half* pBg = g_w13h + ((size_t)e * N13 + n0) * D_;
    const __half* pBu = g_w13h + ((size_t)e * N13 + H_ + n0) * D_;

    float accg[4][4][4], accu[4][4][4];
    #pragma unroll
    for (int i = 0; i < 4; i++)
        #pragma unroll
        for (int j = 0; j < 4; j++)
            #pragma unroll
            for (int p = 0; p < 4; p++) { accg[i][j][p] = 0.f; accu[i][j][p] = 0.f; }

    int r_ld = tid >> 1, c_ld = tid & 1;
    uint32_t soff = swz(r_ld, c_ld);
    size_t gbase = (size_t)r_ld * D_ + c_ld * 8;

    // per-lane ldmatrix row/chunk decomposition
    int a_rl = (lane & 7) + ((lane >> 3) & 1) * 8;   // m within 16-row tile
    int a_ch = lane >> 4;
    int b_rl = lane & 7;                              // n within 8-row frag
    int b_fr = lane >> 4;                             // which nf of the pair
    int b_ch = (lane >> 3) & 1;

    const int NCH = D_ >> 4;   // 48

    #pragma unroll
    for (int c = 0; c < 2; c++) {
        uint32_t sb = smem_u32(sm[c]);
        size_t go = gbase + c * 16;
        cp16(sb + soff,            pA  + go);
        cp16(sb + RGN + soff,      pBg + go);
        cp16(sb + 2 * RGN + soff,  pBu + go);
        asm volatile("cp.async.commit_group;" ::: "memory");
    }

    int stage = 0, pstage = 2;
    for (int c = 0; c < NCH; c++) {
        asm volatile("cp.async.wait_group %0;" :: "n"(1) : "memory");
        __syncthreads();

        if (c + 2 < NCH) {
            uint32_t sbp = smem_u32(sm[pstage]);
            size_t go = gbase + (size_t)(c + 2) * 16;
            cp16(sbp + soff,           pA  + go);
            cp16(sbp + RGN + soff,     pBg + go);
            cp16(sbp + 2 * RGN + soff, pBu + go);
        }
        asm volatile("cp.async.commit_group;" ::: "memory");

        uint32_t sb = smem_u32(sm[stage]);

        // B fragments: j=0 -> nf 0,1 ; j=1 -> nf 2,3. bg[2nf]=b0, bg[2nf+1]=b1.
        uint32_t bg[8], bu[8];
        #pragma unroll
        for (int j = 0; j < 2; j++) {
            int brow = wn * 32 + (2 * j + b_fr) * 8 + b_rl;
            uint32_t ba = sb + RGN + swz(brow, b_ch);
            ldsm4(bg[4 * j], bg[4 * j + 1], bg[4 * j + 2], bg[4 * j + 3], ba);
            ldsm4(bu[4 * j], bu[4 * j + 1], bu[4 * j + 2], bu[4 * j + 3], ba + RGN);
        }
        #pragma unroll
        for (int mf = 0; mf < 4; mf++) {
            int arow = wm * 64 + mf * 16 + a_rl;
            uint32_t ah[4];
            ldsm4(ah[0], ah[1], ah[2], ah[3], sb + swz(arow, a_ch));
            #pragma unroll
            for (int nf = 0; nf < 4; nf++) {
                mma16816(accg[mf][nf], ah, bg[2 * nf], bg[2 * nf + 1]);
                mma16816(accu[mf][nf], ah, bu[2 * nf], bu[2 * nf + 1]);
            }
        }
        stage = (stage == 2) ? 0 : stage + 1;
        pstage = (pstage == 2) ? 0 : pstage + 1;
    }

    __half* Ca = g_acth + ((size_t)e * CAP + m0) * H_ + n0;
    #pragma unroll
    for (int mf = 0; mf < 4; mf++)
        #pragma unroll
        for (int nf = 0; nf < 4; nf++) {
            int r0 = wm * 64 + mf * 16 + g;
            int col = wn * 32 + nf * 8 + q * 2;
            float a0 = silu_mul(accg[mf][nf][0], accu[mf][nf][0]);
            float a1 = silu_mul(accg[mf][nf][1], accu[mf][nf][1]);
            float a2 = silu_mul(accg[mf][nf][2], accu[mf][nf][2]);
            float a3 = silu_mul(accg[mf][nf][3], accu[mf][nf][3]);
            *(__half2*)(Ca + (size_t)r0 * H_ + col)       = __floats2half2_rn(a0, a1);
            *(__half2*)(Ca + (size_t)(r0 + 8) * H_ + col) = __floats2half2_rn(a2, a3);
        }
}

// ---------------- 5) GEMM2 (ldmatrix, 3-stage) -----------------------------
__global__ __launch_bounds__(256) void gemm2_mma()
{
    __shared__ __align__(16) char sm[3][STG2];

    const int K = H_, Ntot = D_;
    int e = blockIdx.z;
    int m0 = blockIdx.y * 128;
    if (m0 >= g_cnt[e]) return;
    int n0 = blockIdx.x * 128;

    int tid = threadIdx.x, lane = tid & 31, wid = tid >> 5;
    int wm = wid & 1, wn = wid >> 1;
    int g = lane >> 2, q = lane & 3;

    const __half* pA = g_acth + ((size_t)e * CAP + m0) * K;
    const __half* pB = g_w2h  + ((size_t)e * Ntot + n0) * K;

    float acc[4][4][4];
    #pragma unroll
    for (int i = 0; i < 4; i++)
        #pragma unroll
        for (int j = 0; j < 4; j++)
            #pragma unroll
            for (int p = 0; p < 4; p++) acc[i][j][p] = 0.f;

    int r_ld = tid >> 1, c_ld = tid & 1;
    uint32_t soff = swz(r_ld, c_ld);
    size_t gbase = (size_t)r_ld * K + c_ld * 8;

    int a_rl = (lane & 7) + ((lane >> 3) & 1) * 8;
    int a_ch = lane >> 4;
    int b_rl = lane & 7;
    int b_fr = lane >> 4;
    int b_ch = (lane >> 3) & 1;

    const int NCH = K >> 4;   // 128

    #pragma unroll
    for (int c = 0; c < 2; c++) {
        uint32_t sb = smem_u32(sm[c]);
        size_t go = gbase + c * 16;
        cp16(sb + soff,       pA + go);
        cp16(sb + RGN + soff, pB + go);
        asm volatile("cp.async.commit_group;" ::: "memory");
    }

    int stage = 0, pstage = 2;
    for (int c = 0; c < NCH; c++) {
        asm volatile("cp.async.wait_group %0;" :: "n"(1) : "memory");
        __syncthreads();

        if (c + 2 < NCH) {
            uint32_t sbp = smem_u32(sm[pstage]);
            size_t go = gbase + (size_t)(c + 2) * 16;
            cp16(sbp + soff,       pA + go);
            cp16(sbp + RGN + soff, pB + go);
        }
        asm volatile("cp.async.commit_group;" ::: "memory");

        uint32_t sb = smem_u32(sm[stage]);

        uint32_t bf[8];
        #pragma unroll
        for (int j = 0; j < 2; j++) {
            int brow = wn * 32 + (2 * j + b_fr) * 8 + b_rl;
            ldsm4(bf[4 * j], bf[4 * j + 1], bf[4 * j + 2], bf[4 * j + 3],
                  sb + RGN + swz(brow, b_ch));
        }
        #pragma unroll
        for (int mf = 0; mf < 4; mf++) {
            int arow = wm * 64 + mf * 16 + a_rl;
            uint32_t ah[4];
            ldsm4(ah[0], ah[1], ah[2], ah[3], sb + swz(arow, a_ch));
            #pragma unroll
            for (int nf = 0; nf < 4; nf++)
                mma16816(acc[mf][nf], ah, bf[2 * nf], bf[2 * nf + 1]);
        }
        stage = (stage == 2) ? 0 : stage + 1;
        pstage = (pstage == 2) ? 0 : pstage + 1;
    }

    float* C = g_ffn + ((size_t)e * CAP + m0) * Ntot + n0;
    #pragma unroll
    for (int mf = 0; mf < 4; mf++)
        #pragma unroll
        for (int nf = 0; nf < 4; nf++) {
            int r0 = wm * 64 + mf * 16 + g;
            int col = wn * 32 + nf * 8 + q * 2;
            *(float2*)(C + (size_t)r0 * Ntot + col) =
                make_float2(acc[mf][nf][0], acc[mf][nf][1]);
            *(float2*)(C + (size_t)(r0 + 8) * Ntot + col) =
                make_float2(acc[mf][nf][2], acc[mf][nf][3]);
        }
}

// ---------------- 6) combine ----------------
__global__ void combine_kernel(const float* __restrict__ x, float* __restrict__ out) {
    int t = blockIdx.x;
    int s0 = g_slot[2 * t], s1 = g_slot[2 * t + 1];
    float w0 = g_weight[2 * t], w1 = g_weight[2 * t + 1];
    int i = threadIdx.x;  // 192
    float4 xv = ((const float4*)(x + (size_t)t * D_))[i];
    float rx = 0.f, ry = 0.f, rz = 0.f, rw = 0.f;
    if (s0 >= 0) {
        float4 f = ((const float4*)(g_ffn + (size_t)s0 * D_))[i];
        rx += w0 * (xv.x + f.x); ry += w0 * (xv.y + f.y);
        rz += w0 * (xv.z + f.z); rw += w0 * (xv.w + f.w);
    }
    if (s1 >= 0) {
        float4 f = ((const float4*)(g_ffn + (size_t)s1 * D_))[i];
        rx += w1 * (xv.x + f.x); ry += w1 * (xv.y + f.y);
        rz += w1 * (xv.z + f.z); rw += w1 * (xv.w + f.w);
    }
    ((float4*)(out + (size_t)t * D_))[i] = make_float4(rx, ry, rz, rw);
}

// ---------------- launch (NO __device__ symbols cross the host ABI) --------
extern "C" void kernel_launch(void* const* d_in, const int* in_sizes, int n_in,
                              void* d_out, int out_size) {
    const float* x      = (const float*)d_in[0];
    const float* gate_w = (const float*)d_in[1];
    const float* w13    = (const float*)d_in[2];
    const float* w2     = (const float*)d_in[3];
    const float* norm_w = (const float*)d_in[4];
    float* out = (float*)d_out;

    router_kernel<<<NT / 8, 256>>>(x, gate_w);
    scan_kernel<<<E_, 256>>>();
    dispatch_kernel<<<E_ * CAP, 192>>>(x, norm_w);

    cvt_kernel<<<(E_ * N13 * D_) / 1024, 256>>>(w13, 0);
    cvt_kernel<<<(E_ * D_ * H_) / 1024, 256>>>(w2, 1);

    dim3 g1(H_ / 128, CAP / 128, E_);    // (16, 40, 8): dual-tile gate+up
    gemm1_silu<<<g1, 256>>>();

    dim3 g2(D_ / 128, CAP / 128, E_);    // (6, 40, 8)
    gemm2_mma<<<g2, 256>>>();

    combine_kernel<<<NT, 192>>>(x, out);
}

// round 11
// speedup vs baseline: 5.4210x; 1.0287x over previous
#include <cuda_runtime.h>
#include <cuda_fp16.h>
#include <math.h>
#include <stdint.h>

// ---------------- problem constants ----------------
#define NT   16384
#define NK   32768
#define D_   768
#define H_   2048
#define E_   8
#define CAP  5120
#define EPSF 1e-6f
#define N13  4096

#define ROWB 32          // bytes per smem row (16 halves, XOR swizzle)
#define RGN  4096        // 128 rows * 32B region
#define STG1 12288       // gemm1 stage: A(4K) + Bg(4K) + Bu(4K)
#define STG2 12288       // gemm2 stage: A(4K) + B(8K, 256 rows)

// ---------------- device scratch (referenced ONLY in device code) ----------------
__device__ float  g_scale[NT];
__device__ __half g_zh  [(size_t)E_ * CAP * D_];
__device__ __half g_w13h[(size_t)E_ * N13 * D_];
__device__ __half g_w2h [(size_t)E_ * D_ * H_];
__device__ __half g_acth[(size_t)E_ * CAP * H_];
__device__ float  g_ffn [(size_t)E_ * CAP * D_];
__device__ int    g_rowlist[E_ * CAP];
__device__ int    g_cnt[E_];
__device__ int    g_slot[NK];
__device__ int    g_expert[NK];
__device__ float  g_weight[NK];

// ---------------- helpers ----------------
__device__ __forceinline__ uint32_t smem_u32(const void* p) {
    uint32_t a;
    asm("{ .reg .u64 t; cvta.to.shared.u64 t, %1; cvt.u32.u64 %0, t; }" : "=r"(a) : "l"(p));
    return a;
}
__device__ __forceinline__ void ldsm4(uint32_t& r0, uint32_t& r1, uint32_t& r2, uint32_t& r3,
                                      uint32_t addr) {
    asm volatile("ldmatrix.sync.aligned.m8n8.x4.shared.b16 {%0,%1,%2,%3}, [%4];"
                 : "=r"(r0), "=r"(r1), "=r"(r2), "=r"(r3) : "r"(addr));
}
__device__ __forceinline__ void mma16816(float* d, const uint32_t* a, uint32_t b0, uint32_t b1) {
    asm volatile(
        "mma.sync.aligned.m16n8k16.row.col.f32.f16.f16.f32 "
        "{%0,%1,%2,%3},{%4,%5,%6,%7},{%8,%9},{%0,%1,%2,%3};"
        : "+f"(d[0]), "+f"(d[1]), "+f"(d[2]), "+f"(d[3])
        : "r"(a[0]), "r"(a[1]), "r"(a[2]), "r"(a[3]), "r"(b0), "r"(b1));
}
__device__ __forceinline__ void cp16(uint32_t saddr, const void* g) {
    asm volatile("cp.async.cg.shared.global [%0], [%1], 16;" :: "r"(saddr), "l"(g) : "memory");
}
__device__ __forceinline__ float silu_mul(float g, float u) {
    return u * (g / (1.f + expf(-g)));
}
__device__ __forceinline__ uint32_t swz(int row, int ch) {
    return (uint32_t)row * ROWB + (uint32_t)((ch ^ ((row >> 2) & 1)) << 4);
}

// ---------------- 1) router + fused rms scale ----------------
__global__ void router_kernel(const float* __restrict__ x, const float* __restrict__ gw) {
    __shared__ float sgw[E_ * D_];
    for (int i = threadIdx.x; i < E_ * D_; i += 256) sgw[i] = gw[i];
    __syncthreads();
    int lane = threadIdx.x & 31, warp = threadIdx.x >> 5;
    int t = blockIdx.x * 8 + warp;
    const float* xp = x + (size_t)t * D_;
    float xr[24];
    float ss = 0.f;
    #pragma unroll
    for (int j = 0; j < 24; j++) { xr[j] = xp[lane + 32 * j]; ss += xr[j] * xr[j]; }
    for (int o = 16; o; o >>= 1) ss += __shfl_xor_sync(0xffffffffu, ss, o);
    float logit[E_];
    #pragma unroll
    for (int e = 0; e < E_; e++) {
        float acc = 0.f;
        #pragma unroll
        for (int j = 0; j < 24; j++) acc += xr[j] * sgw[e * D_ + lane + 32 * j];
        for (int o = 16; o; o >>= 1) acc += __shfl_xor_sync(0xffffffffu, acc, o);
        logit[e] = acc;
    }
    if (lane == 0) {
        g_scale[t] = 2.f * rsqrtf(4.f * ss / (float)D_ + EPSF);
        int i0 = 0; float l0 = logit[0];
        #pragma unroll
        for (int e = 1; e < E_; e++) if (logit[e] > l0) { l0 = logit[e]; i0 = e; }
        int i1 = -1; float l1 = -3.0e38f;
        #pragma unroll
        for (int e = 0; e < E_; e++) if (e != i0 && logit[e] > l1) { l1 = logit[e]; i1 = e; }
        float w0 = 1.f / (1.f + expf(l1 - l0));
        g_expert[2 * t]     = i0;
        g_expert[2 * t + 1] = i1;
        g_weight[2 * t]     = w0;
        g_weight[2 * t + 1] = 1.f - w0;
    }
}

// ---------------- 2) capacity scan ----------------
__global__ void scan_kernel() {
    int e = blockIdx.x;
    int tid = threadIdx.x;
    __shared__ int warpsum[8];
    __shared__ int sbase;
    if (tid == 0) sbase = 0;
    __syncthreads();
    for (int i0 = 0; i0 < NK; i0 += 256) {
        int i = i0 + tid;
        int mine = (g_expert[i] == e) ? 1 : 0;
        unsigned m = __ballot_sync(0xffffffffu, mine);
        int lane = tid & 31, w = tid >> 5;
        if (lane == 0) warpsum[w] = __popc(m);
        __syncthreads();
        int off = 0, tot = 0;
        #pragma unroll
        for (int j = 0; j < 8; j++) { int c = warpsum[j]; tot += c; if (j < w) off += c; }
        int rank = sbase + off + __popc(m & ((1u << lane) - 1u));
        if (mine) {
            if (rank < CAP) { g_rowlist[e * CAP + rank] = i; g_slot[i] = e * CAP + rank; }
            else            { g_slot[i] = -1; }
        }
        __syncthreads();
        if (tid == 0) sbase += tot;
    }
    __syncthreads();
    if (tid == 0) g_cnt[e] = (sbase < CAP) ? sbase : CAP;
}

// ---------------- 3) dispatch -> fp16 ----------------
__global__ void dispatch_kernel(const float* __restrict__ x, const float* __restrict__ norm_w) {
    int slot = blockIdx.x;
    int e = slot / CAP, r = slot % CAP;
    if (r >= g_cnt[e]) return;
    int t = g_rowlist[slot] >> 1;
    float sc = g_scale[t];
    int i = threadIdx.x;  // 192 threads * 4 = 768
    float4 a = ((const float4*)(x + (size_t)t * D_))[i];
    float4 b = ((const float4*)(norm_w + (size_t)e * D_))[i];
    union { __half h[4]; uint2 u; } Hh;
    Hh.h[0] = __float2half_rn(a.x * sc * b.x);
    Hh.h[1] = __float2half_rn(a.y * sc * b.y);
    Hh.h[2] = __float2half_rn(a.z * sc * b.z);
    Hh.h[3] = __float2half_rn(a.w * sc * b.w);
    ((uint2*)(g_zh + (size_t)slot * D_))[i] = Hh.u;
}

// ---------------- weights fp32 -> fp16 ----------------
__global__ void cvt_kernel(const float* __restrict__ src, int which) {
    __half* dst = which ? g_w2h : g_w13h;
    int i = blockIdx.x * 256 + threadIdx.x;
    float4 v = ((const float4*)src)[i];
    union { __half h[4]; uint2 u; } H;
    H.h[0] = __float2half_rn(v.x); H.h[1] = __float2half_rn(v.y);
    H.h[2] = __float2half_rn(v.z); H.h[3] = __float2half_rn(v.w);
    ((uint2*)dst)[i] = H.u;
}

// ---------------- 4) GEMM1 fused with silu (ldmatrix, 4-stage) -------------
__global__ __launch_bounds__(256) void gemm1_silu()
{
    __shared__ __align__(16) char sm[4][STG1];

    int e = blockIdx.z;
    int m0 = blockIdx.y * 128;
    if (m0 >= g_cnt[e]) return;
    int n0 = blockIdx.x * 128;

    int tid = threadIdx.x, lane = tid & 31, wid = tid >> 5;
    int wm = wid & 1, wn = wid >> 1;
    int g = lane >> 2, q = lane & 3;

    const __half* pA  = g_zh   + ((size_t)e * CAP + m0) * D_;
    const __half* pBg = g_w13h + ((size_t)e * N13 + n0) * D_;
    const __half* pBu = g_w13h + ((size_t)e * N13 + H_ + n0) * D_;

    float accg[4][4][4], accu[4][4][4];
    #pragma unroll
    for (int i = 0; i < 4; i++)
        #pragma unroll
        for (int j = 0; j < 4; j++)
            #pragma unroll
            for (int p = 0; p < 4; p++) { accg[i][j][p] = 0.f; accu[i][j][p] = 0.f; }

    int r_ld = tid >> 1, c_ld = tid & 1;
    uint32_t soff = swz(r_ld, c_ld);
    size_t gbase = (size_t)r_ld * D_ + c_ld * 8;

    int a_rl = (lane & 7) + ((lane >> 3) & 1) * 8;
    int a_ch = lane >> 4;
    int b_rl = lane & 7;
    int b_fr = lane >> 4;
    int b_ch = (lane >> 3) & 1;

    const int NCH = D_ >> 4;   // 48

    #pragma unroll
    for (int c = 0; c < 3; c++) {
        uint32_t sb = smem_u32(sm[c]);
        size_t go = gbase + c * 16;
        cp16(sb + soff,            pA  + go);
        cp16(sb + RGN + soff,      pBg + go);
        cp16(sb + 2 * RGN + soff,  pBu + go);
        asm volatile("cp.async.commit_group;" ::: "memory");
    }

    for (int c = 0; c < NCH; c++) {
        asm volatile("cp.async.wait_group %0;" :: "n"(2) : "memory");
        __syncthreads();

        if (c + 3 < NCH) {
            uint32_t sbp = smem_u32(sm[(c + 3) & 3]);
            size_t go = gbase + (size_t)(c + 3) * 16;
            cp16(sbp + soff,           pA  + go);
            cp16(sbp + RGN + soff,     pBg + go);
            cp16(sbp + 2 * RGN + soff, pBu + go);
        }
        asm volatile("cp.async.commit_group;" ::: "memory");

        uint32_t sb = smem_u32(sm[c & 3]);

        uint32_t bg[8], bu[8];
        #pragma unroll
        for (int j = 0; j < 2; j++) {
            int brow = wn * 32 + (2 * j + b_fr) * 8 + b_rl;
            uint32_t ba = sb + RGN + swz(brow, b_ch);
            ldsm4(bg[4 * j], bg[4 * j + 1], bg[4 * j + 2], bg[4 * j + 3], ba);
            ldsm4(bu[4 * j], bu[4 * j + 1], bu[4 * j + 2], bu[4 * j + 3], ba + RGN);
        }
        #pragma unroll
        for (int mf = 0; mf < 4; mf++) {
            int arow = wm * 64 + mf * 16 + a_rl;
            uint32_t ah[4];
            ldsm4(ah[0], ah[1], ah[2], ah[3], sb + swz(arow, a_ch));
            #pragma unroll
            for (int nf = 0; nf < 4; nf++) {
                mma16816(accg[mf][nf], ah, bg[2 * nf], bg[2 * nf + 1]);
                mma16816(accu[mf][nf], ah, bu[2 * nf], bu[2 * nf + 1]);
            }
        }
    }

    __half* Ca = g_acth + ((size_t)e * CAP + m0) * H_ + n0;
    #pragma unroll
    for (int mf = 0; mf < 4; mf++)
        #pragma unroll
        for (int nf = 0; nf < 4; nf++) {
            int r0 = wm * 64 + mf * 16 + g;
            int col = wn * 32 + nf * 8 + q * 2;
            float a0 = silu_mul(accg[mf][nf][0], accu[mf][nf][0]);
            float a1 = silu_mul(accg[mf][nf][1], accu[mf][nf][1]);
            float a2 = silu_mul(accg[mf][nf][2], accu[mf][nf][2]);
            float a3 = silu_mul(accg[mf][nf][3], accu[mf][nf][3]);
            *(__half2*)(Ca + (size_t)r0 * H_ + col)       = __floats2half2_rn(a0, a1);
            *(__half2*)(Ca + (size_t)(r0 + 8) * H_ + col) = __floats2half2_rn(a2, a3);
        }
}

// ---------------- 5) GEMM2 (ldmatrix, BN=256, 4-stage) ---------------------
// Tile 128x256: warp grid 2m x 4n, warp tile 64x64. Stage: A 4KB + B 8KB.
__global__ __launch_bounds__(256) void gemm2_mma()
{
    __shared__ __align__(16) char sm[4][STG2];

    const int K = H_, Ntot = D_;
    int e = blockIdx.z;
    int m0 = blockIdx.y * 128;
    if (m0 >= g_cnt[e]) return;
    int n0 = blockIdx.x * 256;

    int tid = threadIdx.x, lane = tid & 31, wid = tid >> 5;
    int wm = wid & 1, wn = wid >> 1;
    int g = lane >> 2, q = lane & 3;

    const __half* pA = g_acth + ((size_t)e * CAP + m0) * K;
    const __half* pB = g_w2h  + ((size_t)e * Ntot + n0) * K;

    float acc[4][8][4];
    #pragma unroll
    for (int i = 0; i < 4; i++)
        #pragma unroll
        for (int j = 0; j < 8; j++)
            #pragma unroll
            for (int p = 0; p < 4; p++) acc[i][j][p] = 0.f;

    // loaders: A 128 rows x 2 chunks (1/thread), B 256 rows x 2 chunks (2/thread)
    int ar_ld = tid >> 1, ac_ld = tid & 1;
    uint32_t a_soff = swz(ar_ld, ac_ld);
    size_t a_gbase = (size_t)ar_ld * K + ac_ld * 8;
    uint32_t b_soff0 = RGN + swz(tid, 0);
    uint32_t b_soff1 = RGN + swz(tid, 1);
    size_t b_gbase = (size_t)tid * K;

    int a_rl = (lane & 7) + ((lane >> 3) & 1) * 8;
    int a_ch = lane >> 4;
    int b_rl = lane & 7;
    int b_fr = lane >> 4;
    int b_ch = (lane >> 3) & 1;

    const int NCH = K >> 4;   // 128

    #pragma unroll
    for (int c = 0; c < 3; c++) {
        uint32_t sb = smem_u32(sm[c]);
        cp16(sb + a_soff,  pA + a_gbase + c * 16);
        cp16(sb + b_soff0, pB + b_gbase + c * 16);
        cp16(sb + b_soff1, pB + b_gbase + c * 16 + 8);
        asm volatile("cp.async.commit_group;" ::: "memory");
    }

    for (int c = 0; c < NCH; c++) {
        asm volatile("cp.async.wait_group %0;" :: "n"(2) : "memory");
        __syncthreads();

        if (c + 3 < NCH) {
            uint32_t sbp = smem_u32(sm[(c + 3) & 3]);
            size_t ko = (size_t)(c + 3) * 16;
            cp16(sbp + a_soff,  pA + a_gbase + ko);
            cp16(sbp + b_soff0, pB + b_gbase + ko);
            cp16(sbp + b_soff1, pB + b_gbase + ko + 8);
        }
        asm volatile("cp.async.commit_group;" ::: "memory");

        uint32_t sb = smem_u32(sm[c & 3]);

        uint32_t bf[16];
        #pragma unroll
        for (int j = 0; j < 4; j++) {
            int brow = wn * 64 + (2 * j + b_fr) * 8 + b_rl;
            ldsm4(bf[4 * j], bf[4 * j + 1], bf[4 * j + 2], bf[4 * j + 3],
                  sb + RGN + swz(brow, b_ch));
        }
        #pragma unroll
        for (int mf = 0; mf < 4; mf++) {
            int arow = wm * 64 + mf * 16 + a_rl;
            uint32_t ah[4];
            ldsm4(ah[0], ah[1], ah[2], ah[3], sb + swz(arow, a_ch));
            #pragma unroll
            for (int nf = 0; nf < 8; nf++)
                mma16816(acc[mf][nf], ah, bf[2 * nf], bf[2 * nf + 1]);
        }
    }

    float* C = g_ffn + ((size_t)e * CAP + m0) * Ntot + n0;
    #pragma unroll
    for (int mf = 0; mf < 4; mf++)
        #pragma unroll
        for (int nf = 0; nf < 8; nf++) {
            int r0 = wm * 64 + mf * 16 + g;
            int col = wn * 64 + nf * 8 + q * 2;
            *(float2*)(C + (size_t)r0 * Ntot + col) =
                make_float2(acc[mf][nf][0], acc[mf][nf][1]);
            *(float2*)(C + (size_t)(r0 + 8) * Ntot + col) =
                make_float2(acc[mf][nf][2], acc[mf][nf][3]);
        }
}

// ---------------- 6) combine ----------------
__global__ void combine_kernel(const float* __restrict__ x, float* __restrict__ out) {
    int t = blockIdx.x;
    int s0 = g_slot[2 * t], s1 = g_slot[2 * t + 1];
    float w0 = g_weight[2 * t], w1 = g_weight[2 * t + 1];
    int i = threadIdx.x;  // 192
    float4 xv = ((const float4*)(x + (size_t)t * D_))[i];
    float rx = 0.f, ry = 0.f, rz = 0.f, rw = 0.f;
    if (s0 >= 0) {
        float4 f = ((const float4*)(g_ffn + (size_t)s0 * D_))[i];
        rx += w0 * (xv.x + f.x); ry += w0 * (xv.y + f.y);
        rz += w0 * (xv.z + f.z); rw += w0 * (xv.w + f.w);
    }
    if (s1 >= 0) {
        float4 f = ((const float4*)(g_ffn + (size_t)s1 * D_))[i];
        rx += w1 * (xv.x + f.x); ry += w1 * (xv.y + f.y);
        rz += w1 * (xv.z + f.z); rw += w1 * (xv.w + f.w);
    }
    ((float4*)(out + (size_t)t * D_))[i] = make_float4(rx, ry, rz, rw);
}

// ---------------- launch (NO __device__ symbols cross the host ABI) --------
extern "C" void kernel_launch(void* const* d_in, const int* in_sizes, int n_in,
                              void* d_out, int out_size) {
    const float* x      = (const float*)d_in[0];
    const float* gate_w = (const float*)d_in[1];
    const float* w13    = (const float*)d_in[2];
    const float* w2     = (const float*)d_in[3];
    const float* norm_w = (const float*)d_in[4];
    float* out = (float*)d_out;

    router_kernel<<<NT / 8, 256>>>(x, gate_w);
    scan_kernel<<<E_, 256>>>();
    dispatch_kernel<<<E_ * CAP, 192>>>(x, norm_w);

    cvt_kernel<<<(E_ * N13 * D_) / 1024, 256>>>(w13, 0);
    cvt_kernel<<<(E_ * D_ * H_) / 1024, 256>>>(w2, 1);

    dim3 g1(H_ / 128, CAP / 128, E_);    // (16, 40, 8): dual-tile gate+up
    gemm1_silu<<<g1, 256>>>();

    dim3 g2(D_ / 256, CAP / 128, E_);    // (3, 40, 8)
    gemm2_mma<<<g2, 256>>>();

    combine_kernel<<<NT, 192>>>(x, out);
}